// round 1
// baseline (speedup 1.0000x reference)
#include <cuda_runtime.h>
#include <math.h>

#define NN 50000
#define EE 800000
#define ET 850000   // EE + NN self loops
#define GG 512

// ---------------- static scratch (no allocations allowed) ----------------
__device__ __align__(128) float g_y1[(size_t)NN * 512];  // [xl1 | xr1]
__device__ __align__(128) float g_h1[(size_t)NN * 256];  // post-ELU layer1 output
__device__ __align__(128) float g_y2[(size_t)NN * 256];  // [xl2 | xr2]
__device__ int    g_deg[NN];
__device__ int    g_off[NN + 1];
__device__ int    g_cur[NN];
__device__ int    g_csrc[ET];
__device__ double g_bnsum[256];
__device__ double g_bnsq[256];
__device__ float  g_scale[256];
__device__ float  g_shift[256];
__device__ float  g_pool[GG * 128];
__device__ float  g_cnt[GG];

// ---------------- init ----------------
__global__ void k_init() {
    int i = blockIdx.x * blockDim.x + threadIdx.x;  // 65536 threads
    if (i < NN) g_deg[i] = 0;
    if (i < GG * 128) g_pool[i] = 0.f;
    if (i < GG) g_cnt[i] = 0.f;
    if (i < 256) { g_bnsum[i] = 0.0; g_bnsq[i] = 0.0; }
}

// ---------------- CSR build ----------------
__global__ void k_hist(const int* __restrict__ ei) {
    int i = blockIdx.x * blockDim.x + threadIdx.x;
    if (i >= ET) return;
    int dst = (i < EE) ? ei[EE + i] : (i - EE);
    atomicAdd(&g_deg[dst], 1);
}

__global__ void k_scan() {
    __shared__ int sh[1024];
    __shared__ int carry;
    int t = threadIdx.x;
    if (t == 0) carry = 0;
    __syncthreads();
    for (int base = 0; base < NN; base += 1024) {
        int i = base + t;
        int v = (i < NN) ? g_deg[i] : 0;
        sh[t] = v;
        __syncthreads();
        for (int off = 1; off < 1024; off <<= 1) {
            int add = (t >= off) ? sh[t - off] : 0;
            __syncthreads();
            sh[t] += add;
            __syncthreads();
        }
        int excl = sh[t] - v;
        if (i < NN) { g_off[i] = carry + excl; g_cur[i] = carry + excl; }
        int total = sh[1023];
        __syncthreads();
        if (t == 0) carry += total;
        __syncthreads();
    }
    if (t == 0) g_off[NN] = carry;
}

__global__ void k_fill(const int* __restrict__ ei) {
    int i = blockIdx.x * blockDim.x + threadIdx.x;
    if (i >= ET) return;
    int src = (i < EE) ? ei[i] : (i - EE);
    int dst = (i < EE) ? ei[EE + i] : (i - EE);
    int p = atomicAdd(&g_cur[dst], 1);
    g_csrc[p] = src;
}

// ---------------- GEMM: C[M,Ncols] = A[M,K] @ B[K,Ncols]  (64x64x16 tiles) ----------------
template <bool NORM>
__global__ void k_gemm(const float* __restrict__ A, int lda,
                       const float* __restrict__ B, int ldb,
                       float* __restrict__ C, int ldc,
                       int M, int K) {
    __shared__ float As[16][68];   // transposed A tile: As[k][m]
    __shared__ float Bs[16][68];
    const int tid = threadIdx.x;
    const int tx = tid & 15, ty = tid >> 4;
    const int row0 = blockIdx.y * 64, col0 = blockIdx.x * 64;
    float acc[4][4] = {};
    for (int k0 = 0; k0 < K; k0 += 16) {
        {
            int r = tid >> 2;
            int kk = (tid & 3) * 4;
            int grow = row0 + r;
            float4 v = make_float4(0.f, 0.f, 0.f, 0.f);
            if (grow < M) {
                v = *(const float4*)(A + (size_t)grow * lda + k0 + kk);
                if (NORM) {
                    v.x = fmaf(v.x, g_scale[k0 + kk + 0], g_shift[k0 + kk + 0]);
                    v.y = fmaf(v.y, g_scale[k0 + kk + 1], g_shift[k0 + kk + 1]);
                    v.z = fmaf(v.z, g_scale[k0 + kk + 2], g_shift[k0 + kk + 2]);
                    v.w = fmaf(v.w, g_scale[k0 + kk + 3], g_shift[k0 + kk + 3]);
                }
            }
            As[kk + 0][r] = v.x; As[kk + 1][r] = v.y;
            As[kk + 2][r] = v.z; As[kk + 3][r] = v.w;
        }
        {
            int r = tid >> 4;
            int cc = (tid & 15) * 4;
            float4 v = *(const float4*)(B + (size_t)(k0 + r) * ldb + col0 + cc);
            *(float4*)&Bs[r][cc] = v;
        }
        __syncthreads();
#pragma unroll
        for (int kk = 0; kk < 16; kk++) {
            float4 a = *(const float4*)&As[kk][ty * 4];
            float4 b = *(const float4*)&Bs[kk][tx * 4];
            float av[4] = {a.x, a.y, a.z, a.w};
            float bv[4] = {b.x, b.y, b.z, b.w};
#pragma unroll
            for (int i = 0; i < 4; i++)
#pragma unroll
                for (int j = 0; j < 4; j++)
                    acc[i][j] = fmaf(av[i], bv[j], acc[i][j]);
        }
        __syncthreads();
    }
#pragma unroll
    for (int i = 0; i < 4; i++) {
        int grow = row0 + ty * 4 + i;
        if (grow < M) {
            float4 v = make_float4(acc[i][0], acc[i][1], acc[i][2], acc[i][3]);
            *(float4*)(C + (size_t)grow * ldc + col0 + tx * 4) = v;
        }
    }
}

// ---------------- GATv2 aggregation: warp per dst node, online softmax ----------------
template <int HEADS, bool FINAL>
__global__ void k_agg(const float* __restrict__ y,      // [NN, 2*CH]  = [xl | xr]
                      const float* __restrict__ att,    // [CH]
                      const float* __restrict__ bias,   // [CH]
                      float* __restrict__ hout,         // [NN, CH]  (if !FINAL)
                      const int* __restrict__ batch) {
    constexpr int CH = HEADS * 128;
    constexpr int R = CH / 32;
    constexpr int HR = R / HEADS;
    const int lane = threadIdx.x & 31;
    const int t = (blockIdx.x * blockDim.x + threadIdx.x) >> 5;
    if (t >= NN) return;

    const float* yt = y + (size_t)t * (2 * CH) + CH;  // xr[t]
    float xr[R], attv[R], acc[R];
#pragma unroll
    for (int r = 0; r < R; r++) {
        int c = lane + 32 * r;
        xr[r] = yt[c];
        attv[r] = att[c];
        acc[r] = 0.f;
    }
    float emax[HEADS], den[HEADS];
#pragma unroll
    for (int h = 0; h < HEADS; h++) { emax[h] = -1e30f; den[h] = 0.f; }

    const int s0 = g_off[t], s1 = g_off[t + 1];
    for (int j = s0; j < s1; j++) {
        int s = g_csrc[j];
        const float* ys = y + (size_t)s * (2 * CH);  // xl[s]
        float xv[R], d[HEADS];
#pragma unroll
        for (int h = 0; h < HEADS; h++) d[h] = 0.f;
#pragma unroll
        for (int r = 0; r < R; r++) {
            float v = ys[lane + 32 * r];
            xv[r] = v;
            float m = v + xr[r];
            m = (m > 0.f) ? m : 0.2f * m;  // leaky relu
            d[r / HR] = fmaf(m, attv[r], d[r / HR]);
        }
#pragma unroll
        for (int h = 0; h < HEADS; h++) {
#pragma unroll
            for (int o = 16; o; o >>= 1) d[h] += __shfl_xor_sync(0xffffffffu, d[h], o);
        }
        float ex[HEADS];
#pragma unroll
        for (int h = 0; h < HEADS; h++) {
            if (d[h] > emax[h]) {
                float corr = __expf(emax[h] - d[h]);
                den[h] *= corr;
#pragma unroll
                for (int r = h * HR; r < (h + 1) * HR; r++) acc[r] *= corr;
                emax[h] = d[h];
                ex[h] = 1.f;
            } else {
                ex[h] = __expf(d[h] - emax[h]);
            }
            den[h] += ex[h];
        }
#pragma unroll
        for (int r = 0; r < R; r++) acc[r] = fmaf(ex[r / HR], xv[r], acc[r]);
    }

    if (FINAL) {
        int g = batch[t];
#pragma unroll
        for (int r = 0; r < R; r++) {
            int c = lane + 32 * r;
            float v = acc[r] / (den[r / HR] + 1e-16f) + bias[c];
            atomicAdd(&g_pool[g * CH + c], v);
        }
        if (lane == 0) atomicAdd(&g_cnt[g], 1.f);
    } else {
#pragma unroll
        for (int r = 0; r < R; r++) {
            int c = lane + 32 * r;
            float v = acc[r] / (den[r / HR] + 1e-16f) + bias[c];
            v = (v > 0.f) ? v : expm1f(v);  // ELU
            hout[(size_t)t * CH + c] = v;
        }
    }
}

// ---------------- BatchNorm stats + finalize ----------------
__global__ void k_bnstats(const float* __restrict__ h) {
    int c = threadIdx.x;  // 256
    float s = 0.f, q = 0.f;
    for (int r = blockIdx.x; r < NN; r += gridDim.x) {
        float v = h[(size_t)r * 256 + c];
        s += v;
        q = fmaf(v, v, q);
    }
    atomicAdd(&g_bnsum[c], (double)s);
    atomicAdd(&g_bnsq[c], (double)q);
}

__global__ void k_bnfin(const float* __restrict__ gamma, const float* __restrict__ beta) {
    int c = threadIdx.x;  // 256
    float mu = (float)(g_bnsum[c] / (double)NN);
    float var = (float)(g_bnsq[c] / (double)NN) - mu * mu;
    float sc = gamma[c] * rsqrtf(var + 1e-5f);
    g_scale[c] = sc;
    g_shift[c] = beta[c] - mu * sc;
}

// ---------------- final: pooled mean @ Wlin + blin ----------------
__global__ void k_final(const float* __restrict__ Wlin, const float* __restrict__ blin,
                        float* __restrict__ out) {
    int g = blockIdx.x;        // GG blocks
    int t = threadIdx.x;       // 128 threads
    float inv = 1.f / fmaxf(g_cnt[g], 1.f);
    float p = g_pool[g * 128 + t] * inv;
    float a0 = p * Wlin[2 * t + 0];
    float a1 = p * Wlin[2 * t + 1];
#pragma unroll
    for (int o = 16; o; o >>= 1) {
        a0 += __shfl_xor_sync(0xffffffffu, a0, o);
        a1 += __shfl_xor_sync(0xffffffffu, a1, o);
    }
    __shared__ float sa[4], sb[4];
    if ((t & 31) == 0) { sa[t >> 5] = a0; sb[t >> 5] = a1; }
    __syncthreads();
    if (t == 0) out[2 * g + 0] = sa[0] + sa[1] + sa[2] + sa[3] + blin[0];
    if (t == 1) out[2 * g + 1] = sb[0] + sb[1] + sb[2] + sb[3] + blin[1];
}

// ---------------- launcher ----------------
extern "C" void kernel_launch(void* const* d_in, const int* in_sizes, int n_in,
                              void* d_out, int out_size) {
    const float* x     = (const float*)d_in[0];
    const int*   ei    = (const int*)d_in[1];
    const int*   batch = (const int*)d_in[2];
    const float* Wl1   = (const float*)d_in[3];
    const float* Wr1   = (const float*)d_in[4];
    const float* att1  = (const float*)d_in[5];
    const float* b1    = (const float*)d_in[6];
    const float* gamma = (const float*)d_in[7];
    const float* beta  = (const float*)d_in[8];
    const float* Wl2   = (const float*)d_in[9];
    const float* Wr2   = (const float*)d_in[10];
    const float* att2  = (const float*)d_in[11];
    const float* b2    = (const float*)d_in[12];
    const float* Wlin  = (const float*)d_in[13];
    const float* blin  = (const float*)d_in[14];
    float* out = (float*)d_out;

    void *p_y1, *p_h1, *p_y2;
    cudaGetSymbolAddress(&p_y1, g_y1);
    cudaGetSymbolAddress(&p_h1, g_h1);
    cudaGetSymbolAddress(&p_y2, g_y2);
    float* y1 = (float*)p_y1;
    float* h1 = (float*)p_h1;
    float* y2 = (float*)p_y2;

    // CSR build (identical topology for both layers)
    k_init<<<256, 256>>>();
    k_hist<<<(ET + 255) / 256, 256>>>(ei);
    k_scan<<<1, 1024>>>();
    k_fill<<<(ET + 255) / 256, 256>>>(ei);

    const int MB = (NN + 63) / 64;  // 782

    // Layer 1: y1 = x @ [Wl1 | Wr1]
    k_gemm<false><<<dim3(4, MB), 256>>>(x, 128, Wl1, 256, y1, 512, NN, 128);
    k_gemm<false><<<dim3(4, MB), 256>>>(x, 128, Wr1, 256, y1 + 256, 512, NN, 128);
    k_agg<2, false><<<(NN * 32 + 255) / 256, 256>>>(y1, att1, b1, h1, nullptr);

    // BatchNorm stats (normalization fused into layer-2 GEMM loads)
    k_bnstats<<<512, 256>>>(h1);
    k_bnfin<<<1, 256>>>(gamma, beta);

    // Layer 2: y2 = bn(h1) @ [Wl2 | Wr2]
    k_gemm<true><<<dim3(2, MB), 256>>>(h1, 256, Wl2, 128, y2, 256, NN, 256);
    k_gemm<true><<<dim3(2, MB), 256>>>(h1, 256, Wr2, 128, y2 + 128, 256, NN, 256);
    k_agg<1, true><<<(NN * 32 + 255) / 256, 256>>>(y2, att2, b2, nullptr, batch);

    // Pool mean + final linear
    k_final<<<GG, 128>>>(Wlin, blin, out);
}

// round 5
// speedup vs baseline: 1.3229x; 1.3229x over previous
#include <cuda_runtime.h>
#include <cuda_bf16.h>
#include <math.h>
#include <stdint.h>

#define NN 50000
#define EE 800000
#define ET 850000   // EE + NN self loops
#define GG 512

// ---------------- static scratch (no allocations allowed) ----------------
__device__ __align__(128) float g_y1[(size_t)NN * 512];  // [xl1 | xr1]
__device__ __align__(128) float g_h1[(size_t)NN * 256];  // post-ELU layer1 output
__device__ __align__(128) float g_y2[(size_t)NN * 256];  // [xl2 | xr2]
__device__ __align__(128) __nv_bfloat16 g_xh[(size_t)NN * 128];
__device__ __align__(128) __nv_bfloat16 g_xl[(size_t)NN * 128];
__device__ __align__(128) __nv_bfloat16 g_h1h[(size_t)NN * 256];
__device__ __align__(128) __nv_bfloat16 g_h1l[(size_t)NN * 256];
__device__ __align__(128) __nv_bfloat16 g_B1h[512 * 128];  // layer1 B^T hi [n][k]
__device__ __align__(128) __nv_bfloat16 g_B1l[512 * 128];
__device__ __align__(128) __nv_bfloat16 g_B2h[256 * 256];  // layer2 B^T hi [n][k]
__device__ __align__(128) __nv_bfloat16 g_B2l[256 * 256];
__device__ int    g_deg[NN];
__device__ int    g_off[NN + 1];
__device__ int    g_cur[NN];
__device__ int    g_csrc[ET];
__device__ double g_bnsum[256];
__device__ double g_bnsq[256];
__device__ float  g_scale[256];
__device__ float  g_shift[256];
__device__ float  g_pool[GG * 128];
__device__ float  g_cnt[GG];

// ---------------- PTX helpers (baseline sm_80/sm_90 features only) ----------------
__device__ __forceinline__ uint32_t smem_u32(const void* p) {
    uint32_t r;
    asm("{ .reg .u64 t; cvta.to.shared.u64 t, %1; cvt.u32.u64 %0, t; }" : "=r"(r) : "l"(p));
    return r;
}
#define CP_ASYNC16(dst, src) \
    asm volatile("cp.async.cg.shared.global [%0], [%1], 16;" :: "r"(dst), "l"(src) : "memory")
#define CP_COMMIT() asm volatile("cp.async.commit_group;" ::: "memory")
#define CP_WAIT(n)  asm volatile("cp.async.wait_group %0;" :: "n"(n) : "memory")
#define LDM_X4(r0, r1, r2, r3, addr) \
    asm volatile("ldmatrix.sync.aligned.m8n8.x4.shared.b16 {%0,%1,%2,%3}, [%4];" \
        : "=r"(r0), "=r"(r1), "=r"(r2), "=r"(r3) : "r"(addr))
#define MMA_BF16(cc, a, b0v, b1v) \
    asm volatile("mma.sync.aligned.m16n8k16.row.col.f32.bf16.bf16.f32 " \
        "{%0,%1,%2,%3}, {%4,%5,%6,%7}, {%8,%9}, {%0,%1,%2,%3};" \
        : "+f"((cc)[0]), "+f"((cc)[1]), "+f"((cc)[2]), "+f"((cc)[3]) \
        : "r"((a)[0]), "r"((a)[1]), "r"((a)[2]), "r"((a)[3]), "r"(b0v), "r"(b1v))

__device__ __forceinline__ void split_bf16(float v, __nv_bfloat16& h, __nv_bfloat16& l) {
    h = __float2bfloat16(v);
    l = __float2bfloat16(v - __bfloat162float(h));
}

// ---------------- init ----------------
__global__ void k_init() {
    int i = blockIdx.x * blockDim.x + threadIdx.x;  // 65536 threads
    if (i < NN) g_deg[i] = 0;
    if (i < GG * 128) g_pool[i] = 0.f;
    if (i < GG) g_cnt[i] = 0.f;
    if (i < 256) { g_bnsum[i] = 0.0; g_bnsq[i] = 0.0; }
}

// ---------------- pre-split & transpose weights (hi/lo bf16) ----------------
__global__ void k_splitB(const float* __restrict__ Wl1, const float* __restrict__ Wr1,
                         const float* __restrict__ Wl2, const float* __restrict__ Wr2) {
    int i = blockIdx.x * blockDim.x + threadIdx.x;  // 131072 threads
    if (i < 512 * 128) {
        int n = i >> 7, k = i & 127;
        float w = (n < 256) ? Wl1[k * 256 + n] : Wr1[k * 256 + (n - 256)];
        split_bf16(w, g_B1h[i], g_B1l[i]);
    } else if (i < 512 * 128 + 256 * 256) {
        int j = i - 512 * 128;
        int n = j >> 8, k = j & 255;
        float w = (n < 128) ? Wl2[k * 128 + n] : Wr2[k * 128 + (n - 128)];
        split_bf16(w, g_B2h[j], g_B2l[j]);
    }
}

// ---------------- pre-split activations ----------------
__global__ void k_splitX(const float* __restrict__ x) {
    for (size_t i = (size_t)blockIdx.x * blockDim.x + threadIdx.x;
         i < (size_t)NN * 128; i += (size_t)gridDim.x * blockDim.x)
        split_bf16(x[i], g_xh[i], g_xl[i]);
}

__global__ void k_splitH(const float* __restrict__ h1) {  // BN affine fused here
    for (size_t i = (size_t)blockIdx.x * blockDim.x + threadIdx.x;
         i < (size_t)NN * 256; i += (size_t)gridDim.x * blockDim.x) {
        int c = (int)(i & 255);
        float v = fmaf(h1[i], g_scale[c], g_shift[c]);
        split_bf16(v, g_h1h[i], g_h1l[i]);
    }
}

// ---------------- CSR build ----------------
__global__ void k_hist(const int* __restrict__ ei) {
    int i = blockIdx.x * blockDim.x + threadIdx.x;
    if (i >= ET) return;
    int dst = (i < EE) ? ei[EE + i] : (i - EE);
    atomicAdd(&g_deg[dst], 1);
}

__global__ void k_scan() {  // 1 block, 1024 threads: serial-per-thread + shuffle scan
    __shared__ int warpsum[32];
    const int t = threadIdx.x;
    const int CH = (NN + 1023) / 1024;  // 49
    int i0 = t * CH;
    int i1 = min(i0 + CH, NN);
    int s = 0;
    for (int i = i0; i < i1; i++) s += g_deg[i];
    int lane = t & 31, w = t >> 5;
    int v = s;
#pragma unroll
    for (int o = 1; o < 32; o <<= 1) {
        int u = __shfl_up_sync(0xffffffffu, v, o);
        if (lane >= o) v += u;
    }
    if (lane == 31) warpsum[w] = v;
    __syncthreads();
    if (w == 0) {
        int x = warpsum[lane];
#pragma unroll
        for (int o = 1; o < 32; o <<= 1) {
            int u = __shfl_up_sync(0xffffffffu, x, o);
            if (lane >= o) x += u;
        }
        warpsum[lane] = x;
    }
    __syncthreads();
    int excl = v - s + (w > 0 ? warpsum[w - 1] : 0);
    int run = excl;
    for (int i = i0; i < i1; i++) {
        int d = g_deg[i];
        g_off[i] = run;
        g_cur[i] = run;
        run += d;
    }
    if (t == 1023) g_off[NN] = run;
}

__global__ void k_fill(const int* __restrict__ ei) {
    int i = blockIdx.x * blockDim.x + threadIdx.x;
    if (i >= ET) return;
    int src = (i < EE) ? ei[i] : (i - EE);
    int dst = (i < EE) ? ei[EE + i] : (i - EE);
    int p = atomicAdd(&g_cur[dst], 1);
    g_csrc[p] = src;
}

// ---------------- bf16 3-pass mma.sync GEMM ----------------
// C[M, ldc] tile (128x128) = (Ah+Al)[M,K] @ (Bh+Bl)^T, Bt: [Ntot][K] bf16.
// 8 warps, 32x64 warp tiles, K chunks of 32, double-buffered cp.async.
// smem per buffer: 4 arrays (Ah,Al,Bh,Bl) of 128 rows x 32 halves, row stride 80B.
template <int K>
__global__ void __launch_bounds__(256, 1) k_mma(
    const __nv_bfloat16* __restrict__ Ah, const __nv_bfloat16* __restrict__ Al,
    const __nv_bfloat16* __restrict__ Bh, const __nv_bfloat16* __restrict__ Bl,
    float* __restrict__ C, int ldc, int M) {
    extern __shared__ __align__(128) char smem[];
    constexpr int NC = K / 32;
    const int tid = threadIdx.x, lane = tid & 31, wid = tid >> 5;
    const int row0 = blockIdx.y * 128, n0 = blockIdx.x * 128;
    const int wm = (wid & 3) * 32, wn = (wid >> 2) * 64;
    const uint32_t sb = smem_u32(smem);

    float c[2][8][4];
#pragma unroll
    for (int mf = 0; mf < 2; mf++)
#pragma unroll
        for (int nf = 0; nf < 8; nf++)
#pragma unroll
            for (int q = 0; q < 4; q++) c[mf][nf][q] = 0.f;

    // ---- async-load helper (as a macro-ish lambda) ----
    auto issue = [&](int ch) {
        const int k0 = ch * 32;
        const uint32_t sbase = sb + (uint32_t)(ch & 1) * 40960u;
        const __nv_bfloat16* srcs[4] = {Ah, Al, Bh, Bl};
#pragma unroll
        for (int arr = 0; arr < 4; arr++) {
            const __nv_bfloat16* sp = srcs[arr];
            int rb = (arr < 2) ? row0 : n0;
#pragma unroll
            for (int j = 0; j < 2; j++) {
                int seg = tid + 256 * j;
                int r = seg >> 2, s = seg & 3;
                int gr = rb + r;
                if (arr < 2) gr = min(gr, M - 1);
                const void* src = sp + (size_t)gr * K + k0 + s * 8;
                uint32_t dst = sbase + (uint32_t)arr * 10240u + (uint32_t)r * 80u + (uint32_t)s * 16u;
                CP_ASYNC16(dst, src);
            }
        }
    };

    issue(0);
    CP_COMMIT();

    // ldmatrix per-lane address pieces
    const int grp = lane >> 3, r8 = lane & 7;
    const uint32_t a_row = (uint32_t)(((grp & 1) ? 8 : 0) + r8);
    const uint32_t a_k16 = (grp & 2) ? 16u : 0u;
    const uint32_t b_row = (uint32_t)(((grp & 2) ? 8 : 0) + r8);
    const uint32_t b_k16 = (grp & 1) ? 16u : 0u;

    for (int ch = 0; ch < NC; ch++) {
        if (ch + 1 < NC) {
            issue(ch + 1);
            CP_COMMIT();
            CP_WAIT(1);
        } else {
            CP_WAIT(0);
        }
        __syncthreads();
        const uint32_t sA = sb + (uint32_t)(ch & 1) * 40960u;
#pragma unroll
        for (int ks = 0; ks < 2; ks++) {
            const uint32_t ko = (uint32_t)ks * 32u;
            uint32_t ah[2][4], al[2][4], bh[4][4], bl[4][4];
#pragma unroll
            for (int mf = 0; mf < 2; mf++) {
                uint32_t addr = sA + ((uint32_t)(wm + mf * 16) + a_row) * 80u + ko + a_k16;
                LDM_X4(ah[mf][0], ah[mf][1], ah[mf][2], ah[mf][3], addr);
                LDM_X4(al[mf][0], al[mf][1], al[mf][2], al[mf][3], addr + 10240u);
            }
#pragma unroll
            for (int pf = 0; pf < 4; pf++) {
                uint32_t addr = sA + 20480u + ((uint32_t)(wn + pf * 16) + b_row) * 80u + ko + b_k16;
                LDM_X4(bh[pf][0], bh[pf][1], bh[pf][2], bh[pf][3], addr);
                LDM_X4(bl[pf][0], bl[pf][1], bl[pf][2], bl[pf][3], addr + 10240u);
            }
#pragma unroll
            for (int mf = 0; mf < 2; mf++)
#pragma unroll
                for (int nf = 0; nf < 8; nf++) {
                    const int pf = nf >> 1, h = (nf & 1) * 2;
                    MMA_BF16(c[mf][nf], ah[mf], bh[pf][h], bh[pf][h + 1]);
                    MMA_BF16(c[mf][nf], ah[mf], bl[pf][h], bl[pf][h + 1]);
                    MMA_BF16(c[mf][nf], al[mf], bh[pf][h], bh[pf][h + 1]);
                }
        }
        __syncthreads();
    }

    // epilogue
    const int g = lane >> 2, tg = lane & 3;
#pragma unroll
    for (int mf = 0; mf < 2; mf++) {
        int row = row0 + wm + mf * 16 + g;
#pragma unroll
        for (int nf = 0; nf < 8; nf++) {
            int col = n0 + wn + nf * 8 + 2 * tg;
            if (row < M)
                *(float2*)(C + (size_t)row * ldc + col) = make_float2(c[mf][nf][0], c[mf][nf][1]);
            if (row + 8 < M)
                *(float2*)(C + (size_t)(row + 8) * ldc + col) = make_float2(c[mf][nf][2], c[mf][nf][3]);
        }
    }
}

// ---------------- GATv2 aggregation: warp per dst node, online softmax ----------------
template <int HEADS, bool FINAL>
__global__ void k_agg(const float* __restrict__ y,      // [NN, 2*CH]  = [xl | xr]
                      const float* __restrict__ att,    // [CH]
                      const float* __restrict__ bias,   // [CH]
                      float* __restrict__ hout,         // [NN, CH]  (if !FINAL)
                      const int* __restrict__ batch) {
    constexpr int CH = HEADS * 128;
    constexpr int R = CH / 32;
    constexpr int HR = R / HEADS;
    const int lane = threadIdx.x & 31;
    const int t = (blockIdx.x * blockDim.x + threadIdx.x) >> 5;
    if (t >= NN) return;

    const float* yt = y + (size_t)t * (2 * CH) + CH;  // xr[t]
    float xr[R], attv[R], acc[R];
#pragma unroll
    for (int r = 0; r < R; r++) {
        int c = lane + 32 * r;
        xr[r] = yt[c];
        attv[r] = att[c];
        acc[r] = 0.f;
    }
    float emax[HEADS], den[HEADS];
#pragma unroll
    for (int h = 0; h < HEADS; h++) { emax[h] = -1e30f; den[h] = 0.f; }

    const int s0 = g_off[t], s1 = g_off[t + 1];
    for (int j = s0; j < s1; j++) {
        int s = g_csrc[j];
        const float* ys = y + (size_t)s * (2 * CH);  // xl[s]
        float xv[R], d[HEADS];
#pragma unroll
        for (int h = 0; h < HEADS; h++) d[h] = 0.f;
#pragma unroll
        for (int r = 0; r < R; r++) {
            float v = ys[lane + 32 * r];
            xv[r] = v;
            float m = v + xr[r];
            m = (m > 0.f) ? m : 0.2f * m;  // leaky relu
            d[r / HR] = fmaf(m, attv[r], d[r / HR]);
        }
#pragma unroll
        for (int h = 0; h < HEADS; h++) {
#pragma unroll
            for (int o = 16; o; o >>= 1) d[h] += __shfl_xor_sync(0xffffffffu, d[h], o);
        }
        float ex[HEADS];
#pragma unroll
        for (int h = 0; h < HEADS; h++) {
            if (d[h] > emax[h]) {
                float corr = __expf(emax[h] - d[h]);
                den[h] *= corr;
#pragma unroll
                for (int r = h * HR; r < (h + 1) * HR; r++) acc[r] *= corr;
                emax[h] = d[h];
                ex[h] = 1.f;
            } else {
                ex[h] = __expf(d[h] - emax[h]);
            }
            den[h] += ex[h];
        }
#pragma unroll
        for (int r = 0; r < R; r++) acc[r] = fmaf(ex[r / HR], xv[r], acc[r]);
    }

    if (FINAL) {
        int g = batch[t];
#pragma unroll
        for (int r = 0; r < R; r++) {
            int c = lane + 32 * r;
            float v = acc[r] / (den[r / HR] + 1e-16f) + bias[c];
            atomicAdd(&g_pool[g * CH + c], v);
        }
        if (lane == 0) atomicAdd(&g_cnt[g], 1.f);
    } else {
#pragma unroll
        for (int r = 0; r < R; r++) {
            int c = lane + 32 * r;
            float v = acc[r] / (den[r / HR] + 1e-16f) + bias[c];
            v = (v > 0.f) ? v : expm1f(v);  // ELU
            hout[(size_t)t * CH + c] = v;
        }
    }
}

// ---------------- BatchNorm stats + finalize ----------------
__global__ void k_bnstats(const float* __restrict__ h) {
    int c = threadIdx.x;  // 256
    float s = 0.f, q = 0.f;
    for (int r = blockIdx.x; r < NN; r += gridDim.x) {
        float v = h[(size_t)r * 256 + c];
        s += v;
        q = fmaf(v, v, q);
    }
    atomicAdd(&g_bnsum[c], (double)s);
    atomicAdd(&g_bnsq[c], (double)q);
}

__global__ void k_bnfin(const float* __restrict__ gamma, const float* __restrict__ beta) {
    int c = threadIdx.x;  // 256
    float mu = (float)(g_bnsum[c] / (double)NN);
    float var = (float)(g_bnsq[c] / (double)NN) - mu * mu;
    float sc = gamma[c] * rsqrtf(var + 1e-5f);
    g_scale[c] = sc;
    g_shift[c] = beta[c] - mu * sc;
}

// ---------------- final: pooled mean @ Wlin + blin ----------------
__global__ void k_final(const float* __restrict__ Wlin, const float* __restrict__ blin,
                        float* __restrict__ out) {
    int g = blockIdx.x;        // GG blocks
    int t = threadIdx.x;       // 128 threads
    float inv = 1.f / fmaxf(g_cnt[g], 1.f);
    float p = g_pool[g * 128 + t] * inv;
    float a0 = p * Wlin[2 * t + 0];
    float a1 = p * Wlin[2 * t + 1];
#pragma unroll
    for (int o = 16; o; o >>= 1) {
        a0 += __shfl_xor_sync(0xffffffffu, a0, o);
        a1 += __shfl_xor_sync(0xffffffffu, a1, o);
    }
    __shared__ float sa[4], sb2[4];
    if ((t & 31) == 0) { sa[t >> 5] = a0; sb2[t >> 5] = a1; }
    __syncthreads();
    if (t == 0) out[2 * g + 0] = sa[0] + sa[1] + sa[2] + sa[3] + blin[0];
    if (t == 1) out[2 * g + 1] = sb2[0] + sb2[1] + sb2[2] + sb2[3] + blin[1];
}

// ---------------- launcher ----------------
extern "C" void kernel_launch(void* const* d_in, const int* in_sizes, int n_in,
                              void* d_out, int out_size) {
    const float* x     = (const float*)d_in[0];
    const int*   ei    = (const int*)d_in[1];
    const int*   batch = (const int*)d_in[2];
    const float* Wl1   = (const float*)d_in[3];
    const float* Wr1   = (const float*)d_in[4];
    const float* att1  = (const float*)d_in[5];
    const float* b1    = (const float*)d_in[6];
    const float* gamma = (const float*)d_in[7];
    const float* beta  = (const float*)d_in[8];
    const float* Wl2   = (const float*)d_in[9];
    const float* Wr2   = (const float*)d_in[10];
    const float* att2  = (const float*)d_in[11];
    const float* b2    = (const float*)d_in[12];
    const float* Wlin  = (const float*)d_in[13];
    const float* blin  = (const float*)d_in[14];
    float* out = (float*)d_out;

    void *p_y1, *p_h1, *p_y2, *p_xh, *p_xl, *p_h1h, *p_h1l;
    void *p_b1h, *p_b1l, *p_b2h, *p_b2l;
    cudaGetSymbolAddress(&p_y1, g_y1);
    cudaGetSymbolAddress(&p_h1, g_h1);
    cudaGetSymbolAddress(&p_y2, g_y2);
    cudaGetSymbolAddress(&p_xh, g_xh);
    cudaGetSymbolAddress(&p_xl, g_xl);
    cudaGetSymbolAddress(&p_h1h, g_h1h);
    cudaGetSymbolAddress(&p_h1l, g_h1l);
    cudaGetSymbolAddress(&p_b1h, g_B1h);
    cudaGetSymbolAddress(&p_b1l, g_B1l);
    cudaGetSymbolAddress(&p_b2h, g_B2h);
    cudaGetSymbolAddress(&p_b2l, g_B2l);
    float* y1 = (float*)p_y1;
    float* h1 = (float*)p_h1;
    float* y2 = (float*)p_y2;

    const int SMEMSZ = 2 * 40960;  // 81920 bytes
    cudaFuncSetAttribute(k_mma<128>, cudaFuncAttributeMaxDynamicSharedMemorySize, SMEMSZ);
    cudaFuncSetAttribute(k_mma<256>, cudaFuncAttributeMaxDynamicSharedMemorySize, SMEMSZ);

    // CSR build + weight/activation split (independent of each other)
    k_init<<<256, 256>>>();
    k_splitB<<<512, 256>>>(Wl1, Wr1, Wl2, Wr2);
    k_splitX<<<2048, 256>>>(x);
    k_hist<<<(ET + 255) / 256, 256>>>(ei);
    k_scan<<<1, 1024>>>();
    k_fill<<<(ET + 255) / 256, 256>>>(ei);

    const int MB = (NN + 127) / 128;  // 391

    // Layer 1: y1 = x @ [Wl1 | Wr1]   (bf16 3-pass mma.sync)
    k_mma<128><<<dim3(4, MB), 256, SMEMSZ>>>(
        (const __nv_bfloat16*)p_xh, (const __nv_bfloat16*)p_xl,
        (const __nv_bfloat16*)p_b1h, (const __nv_bfloat16*)p_b1l, y1, 512, NN);
    k_agg<2, false><<<(NN * 32 + 255) / 256, 256>>>(y1, att1, b1, h1, nullptr);

    // BatchNorm stats -> fold affine into h1 split
    k_bnstats<<<512, 256>>>(h1);
    k_bnfin<<<1, 256>>>(gamma, beta);
    k_splitH<<<2048, 256>>>(h1);

    // Layer 2: y2 = bn(h1) @ [Wl2 | Wr2]
    k_mma<256><<<dim3(2, MB), 256, SMEMSZ>>>(
        (const __nv_bfloat16*)p_h1h, (const __nv_bfloat16*)p_h1l,
        (const __nv_bfloat16*)p_b2h, (const __nv_bfloat16*)p_b2l, y2, 256, NN);
    k_agg<1, true><<<(NN * 32 + 255) / 256, 256>>>(y2, att2, b2, nullptr, batch);

    // Pool mean + final linear
    k_final<<<GG, 128>>>(Wlin, blin, out);
}

// round 6
// speedup vs baseline: 1.3420x; 1.0145x over previous
#include <cuda_runtime.h>
#include <cuda_bf16.h>
#include <math.h>
#include <stdint.h>

#define NN 50000
#define EE 800000
#define ET 850000   // EE + NN self loops
#define GG 512

// ---------------- static scratch (no allocations allowed) ----------------
__device__ __align__(128) float g_y1[(size_t)NN * 512];  // [xl1 | xr1]
__device__ __align__(128) float g_h1[(size_t)NN * 256];  // post-ELU layer1 output
__device__ __align__(128) float g_y2[(size_t)NN * 256];  // [xl2 | xr2]
__device__ __align__(128) __nv_bfloat16 g_B1h[512 * 128];  // layer1 B^T hi [n][k]
__device__ __align__(128) __nv_bfloat16 g_B1l[512 * 128];
__device__ __align__(128) __nv_bfloat16 g_B2h[256 * 256];  // layer2 B^T hi [n][k]
__device__ __align__(128) __nv_bfloat16 g_B2l[256 * 256];
__device__ int    g_deg[NN];
__device__ int    g_off[NN + 1];
__device__ int    g_cur[NN];
__device__ int    g_csrc[ET];
__device__ double g_bnsum[256];
__device__ double g_bnsq[256];
__device__ float  g_scale[256];
__device__ float  g_shift[256];
__device__ float  g_pool[GG * 128];
__device__ float  g_cnt[GG];

// ---------------- PTX helpers (baseline sm_80/sm_90 features only) ----------------
__device__ __forceinline__ uint32_t smem_u32(const void* p) {
    uint32_t r;
    asm("{ .reg .u64 t; cvta.to.shared.u64 t, %1; cvt.u32.u64 %0, t; }" : "=r"(r) : "l"(p));
    return r;
}
#define CP_ASYNC16(dst, src) \
    asm volatile("cp.async.cg.shared.global [%0], [%1], 16;" :: "r"(dst), "l"(src) : "memory")
#define CP_COMMIT() asm volatile("cp.async.commit_group;" ::: "memory")
#define CP_WAIT(n)  asm volatile("cp.async.wait_group %0;" :: "n"(n) : "memory")
#define LDM_X4(r0, r1, r2, r3, addr) \
    asm volatile("ldmatrix.sync.aligned.m8n8.x4.shared.b16 {%0,%1,%2,%3}, [%4];" \
        : "=r"(r0), "=r"(r1), "=r"(r2), "=r"(r3) : "r"(addr))
#define MMA_BF16(cc, a, b0v, b1v) \
    asm volatile("mma.sync.aligned.m16n8k16.row.col.f32.bf16.bf16.f32 " \
        "{%0,%1,%2,%3}, {%4,%5,%6,%7}, {%8,%9}, {%0,%1,%2,%3};" \
        : "+f"((cc)[0]), "+f"((cc)[1]), "+f"((cc)[2]), "+f"((cc)[3]) \
        : "r"((a)[0]), "r"((a)[1]), "r"((a)[2]), "r"((a)[3]), "r"(b0v), "r"(b1v))

__device__ __forceinline__ void split_bf16(float v, __nv_bfloat16& h, __nv_bfloat16& l) {
    h = __float2bfloat16(v);
    l = __float2bfloat16(v - __bfloat162float(h));
}
__device__ __forceinline__ uint32_t pk2(float a, float b) {
    __nv_bfloat162 t = __floats2bfloat162_rn(a, b);
    return *reinterpret_cast<uint32_t*>(&t);
}

// ---------------- init ----------------
__global__ void k_init() {
    int i = blockIdx.x * blockDim.x + threadIdx.x;  // 65536 threads
    if (i < NN) g_deg[i] = 0;
    if (i < GG * 128) g_pool[i] = 0.f;
    if (i < GG) g_cnt[i] = 0.f;
    if (i < 256) { g_bnsum[i] = 0.0; g_bnsq[i] = 0.0; }
}

// ---------------- pre-split & transpose weights (hi/lo bf16) ----------------
__global__ void k_splitB(const float* __restrict__ Wl1, const float* __restrict__ Wr1,
                         const float* __restrict__ Wl2, const float* __restrict__ Wr2) {
    int i = blockIdx.x * blockDim.x + threadIdx.x;  // 131072 threads
    if (i < 512 * 128) {
        int n = i >> 7, k = i & 127;
        float w = (n < 256) ? Wl1[k * 256 + n] : Wr1[k * 256 + (n - 256)];
        split_bf16(w, g_B1h[i], g_B1l[i]);
    } else if (i < 512 * 128 + 256 * 256) {
        int j = i - 512 * 128;
        int n = j >> 8, k = j & 255;
        float w = (n < 128) ? Wl2[k * 128 + n] : Wr2[k * 128 + (n - 128)];
        split_bf16(w, g_B2h[j], g_B2l[j]);
    }
}

// ---------------- CSR build ----------------
__global__ void k_hist(const int* __restrict__ ei) {
    int i = blockIdx.x * blockDim.x + threadIdx.x;
    if (i >= ET) return;
    int dst = (i < EE) ? ei[EE + i] : (i - EE);
    atomicAdd(&g_deg[dst], 1);
}

__global__ void k_scan() {  // 1 block, 1024 threads: serial-per-thread + shuffle scan
    __shared__ int warpsum[32];
    const int t = threadIdx.x;
    const int CH = (NN + 1023) / 1024;  // 49
    int i0 = t * CH;
    int i1 = min(i0 + CH, NN);
    int s = 0;
    for (int i = i0; i < i1; i++) s += g_deg[i];
    int lane = t & 31, w = t >> 5;
    int v = s;
#pragma unroll
    for (int o = 1; o < 32; o <<= 1) {
        int u = __shfl_up_sync(0xffffffffu, v, o);
        if (lane >= o) v += u;
    }
    if (lane == 31) warpsum[w] = v;
    __syncthreads();
    if (w == 0) {
        int x = warpsum[lane];
#pragma unroll
        for (int o = 1; o < 32; o <<= 1) {
            int u = __shfl_up_sync(0xffffffffu, x, o);
            if (lane >= o) x += u;
        }
        warpsum[lane] = x;
    }
    __syncthreads();
    int excl = v - s + (w > 0 ? warpsum[w - 1] : 0);
    int run = excl;
    for (int i = i0; i < i1; i++) {
        int d = g_deg[i];
        g_off[i] = run;
        g_cur[i] = run;
        run += d;
    }
    if (t == 1023) g_off[NN] = run;
}

__global__ void k_fill(const int* __restrict__ ei) {
    int i = blockIdx.x * blockDim.x + threadIdx.x;
    if (i >= ET) return;
    int src = (i < EE) ? ei[i] : (i - EE);
    int dst = (i < EE) ? ei[EE + i] : (i - EE);
    int p = atomicAdd(&g_cur[dst], 1);
    g_csrc[p] = src;
}

// ---------------- bf16 3-pass mma.sync GEMM with in-register A split ----------------
// C tile (128x128) = (Ah+Al)[M,K] @ (Bh+Bl)^T.  A is fp32 [M,K], split on the fly
// (optionally BN-normalized first). Bh/Bl: pre-split bf16 [Ntot][K].
// 8 warps, 32x64 warp tiles, K chunks of 32, double-buffered (A via reg prefetch,
// B via cp.async). smem buffer: Ah | Al | Bh | Bl, 128 rows x 32 halves, stride 80B.
template <int K, bool NORM>
__global__ void __launch_bounds__(256, 1) k_mma(
    const float* __restrict__ A,
    const __nv_bfloat16* __restrict__ Bh, const __nv_bfloat16* __restrict__ Bl,
    float* __restrict__ C, int ldc, int M) {
    extern __shared__ __align__(128) char smem[];
    constexpr int NC = K / 32;
    const int tid = threadIdx.x, lane = tid & 31, wid = tid >> 5;
    const int row0 = blockIdx.y * 128, n0 = blockIdx.x * 128;
    const int wm = (wid & 3) * 32, wn = (wid >> 2) * 64;
    const uint32_t sb = smem_u32(smem);
    float* sScale = (float*)(smem + 81920);
    float* sShift = (float*)(smem + 81920 + 1024);

    if (NORM) {
        if (tid < K) { sScale[tid] = g_scale[tid]; sShift[tid] = g_shift[tid]; }
        __syncthreads();
    }

    float c[2][8][4];
#pragma unroll
    for (int mf = 0; mf < 2; mf++)
#pragma unroll
        for (int nf = 0; nf < 8; nf++)
#pragma unroll
            for (int q = 0; q < 4; q++) c[mf][nf][q] = 0.f;

    const int ar = tid >> 1;             // A row within tile
    const int ac = (tid & 1) * 16;       // A col-seg within chunk
    const int agr = min(row0 + ar, M - 1);

    auto ldgA = [&](int ch, float* f) {
        const float* ap = A + (size_t)agr * K + ch * 32 + ac;
#pragma unroll
        for (int q = 0; q < 4; q++) {
            float4 v = *(const float4*)(ap + q * 4);
            f[q * 4 + 0] = v.x; f[q * 4 + 1] = v.y;
            f[q * 4 + 2] = v.z; f[q * 4 + 3] = v.w;
        }
    };
    auto stsA = [&](int ch, float* f) {
        const uint32_t base = sb + (uint32_t)(ch & 1) * 40960u;
        if (NORM) {
            const int c0 = ch * 32 + ac;
#pragma unroll
            for (int i = 0; i < 16; i++) f[i] = fmaf(f[i], sScale[c0 + i], sShift[c0 + i]);
        }
        float h[16], l[16];
#pragma unroll
        for (int i = 0; i < 16; i++) {
            __nv_bfloat16 hb = __float2bfloat16(f[i]);
            h[i] = __bfloat162float(hb);
            l[i] = f[i] - h[i];
        }
        const uint32_t ad = base + (uint32_t)ar * 80u + (uint32_t)ac * 2u;
        uint4 H0 = make_uint4(pk2(h[0], h[1]), pk2(h[2], h[3]), pk2(h[4], h[5]), pk2(h[6], h[7]));
        uint4 H1 = make_uint4(pk2(h[8], h[9]), pk2(h[10], h[11]), pk2(h[12], h[13]), pk2(h[14], h[15]));
        uint4 L0 = make_uint4(pk2(l[0], l[1]), pk2(l[2], l[3]), pk2(l[4], l[5]), pk2(l[6], l[7]));
        uint4 L1 = make_uint4(pk2(l[8], l[9]), pk2(l[10], l[11]), pk2(l[12], l[13]), pk2(l[14], l[15]));
        *(uint4*)(smem + (ad - sb)) = H0;
        *(uint4*)(smem + (ad - sb) + 16) = H1;
        *(uint4*)(smem + (ad - sb) + 10240) = L0;
        *(uint4*)(smem + (ad - sb) + 10240 + 16) = L1;
    };
    auto issueB = [&](int ch) {
        const int k0 = ch * 32;
        const uint32_t base = sb + (uint32_t)(ch & 1) * 40960u + 20480u;
#pragma unroll
        for (int j = 0; j < 2; j++) {
            int seg = tid + 256 * j;
            int r = seg >> 2, s = seg & 3;
            const void* srch = Bh + (size_t)(n0 + r) * K + k0 + s * 8;
            const void* srcl = Bl + (size_t)(n0 + r) * K + k0 + s * 8;
            uint32_t dst = base + (uint32_t)r * 80u + (uint32_t)s * 16u;
            CP_ASYNC16(dst, srch);
            CP_ASYNC16(dst + 10240u, srcl);
        }
    };

    // prologue
    float areg[16];
    ldgA(0, areg);
    stsA(0, areg);
    issueB(0);
    CP_COMMIT();
    if (NC > 1) {
        issueB(1);
        CP_COMMIT();
        ldgA(1, areg);
    }

    // ldmatrix per-lane address pieces
    const int grp = lane >> 3, r8 = lane & 7;
    const uint32_t a_row = (uint32_t)(((grp & 1) ? 8 : 0) + r8);
    const uint32_t a_k16 = (grp & 2) ? 16u : 0u;
    const uint32_t b_row = (uint32_t)(((grp & 2) ? 8 : 0) + r8);
    const uint32_t b_k16 = (grp & 1) ? 16u : 0u;

    for (int ch = 0; ch < NC; ch++) {
        if (ch + 1 < NC) { CP_WAIT(1); } else { CP_WAIT(0); }
        __syncthreads();
        const uint32_t sA = sb + (uint32_t)(ch & 1) * 40960u;
#pragma unroll
        for (int ks = 0; ks < 2; ks++) {
            const uint32_t ko = (uint32_t)ks * 32u;
            uint32_t ah[2][4], al[2][4], bh[4][4], bl[4][4];
#pragma unroll
            for (int mf = 0; mf < 2; mf++) {
                uint32_t addr = sA + ((uint32_t)(wm + mf * 16) + a_row) * 80u + ko + a_k16;
                LDM_X4(ah[mf][0], ah[mf][1], ah[mf][2], ah[mf][3], addr);
                LDM_X4(al[mf][0], al[mf][1], al[mf][2], al[mf][3], addr + 10240u);
            }
#pragma unroll
            for (int pf = 0; pf < 4; pf++) {
                uint32_t addr = sA + 20480u + ((uint32_t)(wn + pf * 16) + b_row) * 80u + ko + b_k16;
                LDM_X4(bh[pf][0], bh[pf][1], bh[pf][2], bh[pf][3], addr);
                LDM_X4(bl[pf][0], bl[pf][1], bl[pf][2], bl[pf][3], addr + 10240u);
            }
#pragma unroll
            for (int mf = 0; mf < 2; mf++)
#pragma unroll
                for (int nf = 0; nf < 8; nf++) {
                    const int pf = nf >> 1, h = (nf & 1) * 2;
                    MMA_BF16(c[mf][nf], ah[mf], bh[pf][h], bh[pf][h + 1]);
                    MMA_BF16(c[mf][nf], ah[mf], bl[pf][h], bl[pf][h + 1]);
                    MMA_BF16(c[mf][nf], al[mf], bh[pf][h], bh[pf][h + 1]);
                }
        }
        if (ch + 1 < NC) {
            stsA(ch + 1, areg);               // other buffer: safe pre-sync
            if (ch + 2 < NC) ldgA(ch + 2, areg);
        }
        __syncthreads();
        if (ch + 2 < NC) {
            issueB(ch + 2);                    // reuses buffer (ch&1): safe post-sync
            CP_COMMIT();
        }
    }

    // epilogue
    const int g = lane >> 2, tg = lane & 3;
#pragma unroll
    for (int mf = 0; mf < 2; mf++) {
        int row = row0 + wm + mf * 16 + g;
#pragma unroll
        for (int nf = 0; nf < 8; nf++) {
            int col = n0 + wn + nf * 8 + 2 * tg;
            if (row < M)
                *(float2*)(C + (size_t)row * ldc + col) = make_float2(c[mf][nf][0], c[mf][nf][1]);
            if (row + 8 < M)
                *(float2*)(C + (size_t)(row + 8) * ldc + col) = make_float2(c[mf][nf][2], c[mf][nf][3]);
        }
    }
}

// ---------------- GATv2 aggregation: warp per dst node, online softmax ----------------
template <int HEADS, bool FINAL>
__global__ void k_agg(const float* __restrict__ y,      // [NN, 2*CH]  = [xl | xr]
                      const float* __restrict__ att,    // [CH]
                      const float* __restrict__ bias,   // [CH]
                      float* __restrict__ hout,         // [NN, CH]  (if !FINAL)
                      const int* __restrict__ batch) {
    constexpr int CH = HEADS * 128;
    constexpr int R = CH / 32;
    constexpr int HR = R / HEADS;
    const int lane = threadIdx.x & 31;
    const int t = (blockIdx.x * blockDim.x + threadIdx.x) >> 5;
    if (t >= NN) return;

    const float* yt = y + (size_t)t * (2 * CH) + CH;  // xr[t]
    float xr[R], attv[R], acc[R];
#pragma unroll
    for (int r = 0; r < R; r++) {
        int c = lane + 32 * r;
        xr[r] = yt[c];
        attv[r] = att[c];
        acc[r] = 0.f;
    }
    float emax[HEADS], den[HEADS];
#pragma unroll
    for (int h = 0; h < HEADS; h++) { emax[h] = -1e30f; den[h] = 0.f; }

    const int s0 = g_off[t], s1 = g_off[t + 1];
#pragma unroll 2
    for (int j = s0; j < s1; j++) {
        int s = g_csrc[j];
        const float* ys = y + (size_t)s * (2 * CH);  // xl[s]
        float xv[R], d[HEADS];
#pragma unroll
        for (int h = 0; h < HEADS; h++) d[h] = 0.f;
#pragma unroll
        for (int r = 0; r < R; r++) {
            float v = ys[lane + 32 * r];
            xv[r] = v;
            float m = v + xr[r];
            m = (m > 0.f) ? m : 0.2f * m;  // leaky relu
            d[r / HR] = fmaf(m, attv[r], d[r / HR]);
        }
#pragma unroll
        for (int h = 0; h < HEADS; h++) {
#pragma unroll
            for (int o = 16; o; o >>= 1) d[h] += __shfl_xor_sync(0xffffffffu, d[h], o);
        }
        float ex[HEADS];
#pragma unroll
        for (int h = 0; h < HEADS; h++) {
            if (d[h] > emax[h]) {
                float corr = __expf(emax[h] - d[h]);
                den[h] *= corr;
#pragma unroll
                for (int r = h * HR; r < (h + 1) * HR; r++) acc[r] *= corr;
                emax[h] = d[h];
                ex[h] = 1.f;
            } else {
                ex[h] = __expf(d[h] - emax[h]);
            }
            den[h] += ex[h];
        }
#pragma unroll
        for (int r = 0; r < R; r++) acc[r] = fmaf(ex[r / HR], xv[r], acc[r]);
    }

    if (FINAL) {
        int g = batch[t];
#pragma unroll
        for (int r = 0; r < R; r++) {
            int c = lane + 32 * r;
            float v = acc[r] / (den[r / HR] + 1e-16f) + bias[c];
            atomicAdd(&g_pool[g * CH + c], v);
        }
        if (lane == 0) atomicAdd(&g_cnt[g], 1.f);
    } else {
#pragma unroll
        for (int r = 0; r < R; r++) {
            int c = lane + 32 * r;
            float v = acc[r] / (den[r / HR] + 1e-16f) + bias[c];
            v = (v > 0.f) ? v : expm1f(v);  // ELU
            hout[(size_t)t * CH + c] = v;
        }
    }
}

// ---------------- BatchNorm stats + finalize ----------------
__global__ void k_bnstats(const float* __restrict__ h) {
    int c = threadIdx.x;  // 256
    float s = 0.f, q = 0.f;
    for (int r = blockIdx.x; r < NN; r += gridDim.x) {
        float v = h[(size_t)r * 256 + c];
        s += v;
        q = fmaf(v, v, q);
    }
    atomicAdd(&g_bnsum[c], (double)s);
    atomicAdd(&g_bnsq[c], (double)q);
}

__global__ void k_bnfin(const float* __restrict__ gamma, const float* __restrict__ beta) {
    int c = threadIdx.x;  // 256
    float mu = (float)(g_bnsum[c] / (double)NN);
    float var = (float)(g_bnsq[c] / (double)NN) - mu * mu;
    float sc = gamma[c] * rsqrtf(var + 1e-5f);
    g_scale[c] = sc;
    g_shift[c] = beta[c] - mu * sc;
}

// ---------------- final: pooled mean @ Wlin + blin ----------------
__global__ void k_final(const float* __restrict__ Wlin, const float* __restrict__ blin,
                        float* __restrict__ out) {
    int g = blockIdx.x;        // GG blocks
    int t = threadIdx.x;       // 128 threads
    float inv = 1.f / fmaxf(g_cnt[g], 1.f);
    float p = g_pool[g * 128 + t] * inv;
    float a0 = p * Wlin[2 * t + 0];
    float a1 = p * Wlin[2 * t + 1];
#pragma unroll
    for (int o = 16; o; o >>= 1) {
        a0 += __shfl_xor_sync(0xffffffffu, a0, o);
        a1 += __shfl_xor_sync(0xffffffffu, a1, o);
    }
    __shared__ float sa[4], sb2[4];
    if ((t & 31) == 0) { sa[t >> 5] = a0; sb2[t >> 5] = a1; }
    __syncthreads();
    if (t == 0) out[2 * g + 0] = sa[0] + sa[1] + sa[2] + sa[3] + blin[0];
    if (t == 1) out[2 * g + 1] = sb2[0] + sb2[1] + sb2[2] + sb2[3] + blin[1];
}

// ---------------- launcher ----------------
extern "C" void kernel_launch(void* const* d_in, const int* in_sizes, int n_in,
                              void* d_out, int out_size) {
    const float* x     = (const float*)d_in[0];
    const int*   ei    = (const int*)d_in[1];
    const int*   batch = (const int*)d_in[2];
    const float* Wl1   = (const float*)d_in[3];
    const float* Wr1   = (const float*)d_in[4];
    const float* att1  = (const float*)d_in[5];
    const float* b1    = (const float*)d_in[6];
    const float* gamma = (const float*)d_in[7];
    const float* beta  = (const float*)d_in[8];
    const float* Wl2   = (const float*)d_in[9];
    const float* Wr2   = (const float*)d_in[10];
    const float* att2  = (const float*)d_in[11];
    const float* b2    = (const float*)d_in[12];
    const float* Wlin  = (const float*)d_in[13];
    const float* blin  = (const float*)d_in[14];
    float* out = (float*)d_out;

    void *p_y1, *p_h1, *p_y2, *p_b1h, *p_b1l, *p_b2h, *p_b2l;
    cudaGetSymbolAddress(&p_y1, g_y1);
    cudaGetSymbolAddress(&p_h1, g_h1);
    cudaGetSymbolAddress(&p_y2, g_y2);
    cudaGetSymbolAddress(&p_b1h, g_B1h);
    cudaGetSymbolAddress(&p_b1l, g_B1l);
    cudaGetSymbolAddress(&p_b2h, g_B2h);
    cudaGetSymbolAddress(&p_b2l, g_B2l);
    float* y1 = (float*)p_y1;
    float* h1 = (float*)p_h1;
    float* y2 = (float*)p_y2;

    const int SMEMSZ = 81920 + 2048;  // 2 pipeline buffers + BN scale/shift
    cudaFuncSetAttribute(k_mma<128, false>, cudaFuncAttributeMaxDynamicSharedMemorySize, SMEMSZ);
    cudaFuncSetAttribute(k_mma<256, true>, cudaFuncAttributeMaxDynamicSharedMemorySize, SMEMSZ);

    // CSR build + weight split
    k_init<<<256, 256>>>();
    k_splitB<<<512, 256>>>(Wl1, Wr1, Wl2, Wr2);
    k_hist<<<(ET + 255) / 256, 256>>>(ei);
    k_scan<<<1, 1024>>>();
    k_fill<<<(ET + 255) / 256, 256>>>(ei);

    const int MB = (NN + 127) / 128;  // 391

    // Layer 1: y1 = x @ [Wl1 | Wr1]   (bf16 3-pass mma.sync, in-reg A split)
    k_mma<128, false><<<dim3(4, MB), 256, SMEMSZ>>>(
        x, (const __nv_bfloat16*)p_b1h, (const __nv_bfloat16*)p_b1l, y1, 512, NN);
    k_agg<2, false><<<(NN * 32 + 255) / 256, 256>>>(y1, att1, b1, h1, nullptr);

    // BatchNorm stats -> affine folded into layer-2 GEMM A-loads
    k_bnstats<<<512, 256>>>(h1);
    k_bnfin<<<1, 256>>>(gamma, beta);

    // Layer 2: y2 = bn(h1) @ [Wl2 | Wr2]
    k_mma<256, true><<<dim3(2, MB), 256, SMEMSZ>>>(
        h1, (const __nv_bfloat16*)p_b2h, (const __nv_bfloat16*)p_b2l, y2, 256, NN);
    k_agg<1, true><<<(NN * 32 + 255) / 256, 256>>>(y2, att2, b2, nullptr, batch);

    // Pool mean + final linear
    k_final<<<GG, 128>>>(Wlin, blin, out);
}

// round 7
// speedup vs baseline: 1.5350x; 1.1438x over previous
#include <cuda_runtime.h>
#include <cuda_bf16.h>
#include <math.h>
#include <stdint.h>

#define NN 50000
#define EE 800000
#define ET 850000   // EE + NN self loops
#define GG 512
#define SCB 25      // scan blocks (2048 elems each)

// ---------------- static scratch (no allocations allowed) ----------------
__device__ __align__(128) float g_y1[(size_t)NN * 512];  // [xl1 | xr1]
__device__ __align__(128) float g_h1[(size_t)NN * 256];  // post-ELU layer1 output
__device__ __align__(128) float g_y2[(size_t)NN * 256];  // [xl2 | xr2]
__device__ __align__(128) __nv_bfloat16 g_B1h[512 * 128];  // layer1 B^T hi [n][k]
__device__ __align__(128) __nv_bfloat16 g_B1l[512 * 128];
__device__ __align__(128) __nv_bfloat16 g_B2h[256 * 256];  // layer2 B^T hi [n][k]
__device__ __align__(128) __nv_bfloat16 g_B2l[256 * 256];
__device__ int    g_deg[NN];
__device__ int    g_off[NN + 1];
__device__ int    g_cur[NN];
__device__ int    g_csrc[ET];
__device__ int    g_blksum[32];
__device__ double g_bnsum[256];
__device__ double g_bnsq[256];
__device__ float  g_scale[256];
__device__ float  g_shift[256];
__device__ float  g_pool[GG * 128];
__device__ float  g_cnt[GG];

// ---------------- PTX helpers (baseline sm_80/sm_90 features only) ----------------
__device__ __forceinline__ uint32_t smem_u32(const void* p) {
    uint32_t r;
    asm("{ .reg .u64 t; cvta.to.shared.u64 t, %1; cvt.u32.u64 %0, t; }" : "=r"(r) : "l"(p));
    return r;
}
#define CP_ASYNC16(dst, src) \
    asm volatile("cp.async.cg.shared.global [%0], [%1], 16;" :: "r"(dst), "l"(src) : "memory")
#define CP_COMMIT() asm volatile("cp.async.commit_group;" ::: "memory")
#define CP_WAIT(n)  asm volatile("cp.async.wait_group %0;" :: "n"(n) : "memory")
#define LDM_X4(r0, r1, r2, r3, addr) \
    asm volatile("ldmatrix.sync.aligned.m8n8.x4.shared.b16 {%0,%1,%2,%3}, [%4];" \
        : "=r"(r0), "=r"(r1), "=r"(r2), "=r"(r3) : "r"(addr))
#define MMA_BF16(cc, a, b0v, b1v) \
    asm volatile("mma.sync.aligned.m16n8k16.row.col.f32.bf16.bf16.f32 " \
        "{%0,%1,%2,%3}, {%4,%5,%6,%7}, {%8,%9}, {%0,%1,%2,%3};" \
        : "+f"((cc)[0]), "+f"((cc)[1]), "+f"((cc)[2]), "+f"((cc)[3]) \
        : "r"((a)[0]), "r"((a)[1]), "r"((a)[2]), "r"((a)[3]), "r"(b0v), "r"(b1v))

__device__ __forceinline__ void split_bf16(float v, __nv_bfloat16& h, __nv_bfloat16& l) {
    h = __float2bfloat16(v);
    l = __float2bfloat16(v - __bfloat162float(h));
}
__device__ __forceinline__ uint32_t pk2(float a, float b) {
    __nv_bfloat162 t = __floats2bfloat162_rn(a, b);
    return *reinterpret_cast<uint32_t*>(&t);
}

// ---------------- init ----------------
__global__ void k_init() {
    int i = blockIdx.x * blockDim.x + threadIdx.x;  // 65536 threads
    if (i < NN) g_deg[i] = 0;
    if (i < GG * 128) g_pool[i] = 0.f;
    if (i < GG) g_cnt[i] = 0.f;
    if (i < 256) { g_bnsum[i] = 0.0; g_bnsq[i] = 0.0; }
}

// ---------------- pre-split & transpose weights (hi/lo bf16) ----------------
__global__ void k_splitB(const float* __restrict__ Wl1, const float* __restrict__ Wr1,
                         const float* __restrict__ Wl2, const float* __restrict__ Wr2) {
    int i = blockIdx.x * blockDim.x + threadIdx.x;  // 131072 threads
    if (i < 512 * 128) {
        int n = i >> 7, k = i & 127;
        float w = (n < 256) ? Wl1[k * 256 + n] : Wr1[k * 256 + (n - 256)];
        split_bf16(w, g_B1h[i], g_B1l[i]);
    } else if (i < 512 * 128 + 256 * 256) {
        int j = i - 512 * 128;
        int n = j >> 8, k = j & 255;
        float w = (n < 128) ? Wl2[k * 128 + n] : Wr2[k * 128 + (n - 128)];
        split_bf16(w, g_B2h[j], g_B2l[j]);
    }
}

// ---------------- CSR build ----------------
__global__ void k_hist(const int* __restrict__ ei) {
    int i = blockIdx.x * blockDim.x + threadIdx.x;
    if (i >= ET) return;
    int dst = (i < EE) ? ei[EE + i] : (i - EE);
    atomicAdd(&g_deg[dst], 1);
}

// hierarchical scan: A) block sums, B) scan block sums, C) full scan + write
__global__ void k_scanA() {  // grid SCB, block 1024
    __shared__ int ws[32];
    const int b = blockIdx.x, t = threadIdx.x;
    const int i = b * 2048 + 2 * t;
    int v0 = 0, v1 = 0;
    if (i + 1 < NN) { int2 p = *(const int2*)&g_deg[i]; v0 = p.x; v1 = p.y; }
    else if (i < NN) v0 = g_deg[i];
    int s = v0 + v1;
#pragma unroll
    for (int o = 16; o; o >>= 1) s += __shfl_xor_sync(0xffffffffu, s, o);
    if ((t & 31) == 0) ws[t >> 5] = s;
    __syncthreads();
    if (t < 32) {
        int x = ws[t];
#pragma unroll
        for (int o = 16; o; o >>= 1) x += __shfl_xor_sync(0xffffffffu, x, o);
        if (t == 0) g_blksum[b] = x;
    }
}

__global__ void k_scanB() {  // 1 block, 32 threads: exclusive scan of SCB sums
    int t = threadIdx.x;
    int v = (t < SCB) ? g_blksum[t] : 0;
    int x = v;
#pragma unroll
    for (int o = 1; o < 32; o <<= 1) {
        int u = __shfl_up_sync(0xffffffffu, x, o);
        if (t >= o) x += u;
    }
    if (t < SCB) g_blksum[t] = x - v;  // exclusive
    if (t == SCB - 1) g_off[NN] = x;   // grand total
}

__global__ void k_scanC() {  // grid SCB, block 1024: full scan + write off/cur
    __shared__ int ws[32];
    const int b = blockIdx.x, t = threadIdx.x;
    const int lane = t & 31, w = t >> 5;
    const int i = b * 2048 + 2 * t;
    int v0 = 0, v1 = 0;
    if (i + 1 < NN) { int2 p = *(const int2*)&g_deg[i]; v0 = p.x; v1 = p.y; }
    else if (i < NN) v0 = g_deg[i];
    int s = v0 + v1;
    int x = s;
#pragma unroll
    for (int o = 1; o < 32; o <<= 1) {
        int u = __shfl_up_sync(0xffffffffu, x, o);
        if (lane >= o) x += u;
    }
    if (lane == 31) ws[w] = x;
    __syncthreads();
    if (w == 0) {
        int y = ws[lane];
#pragma unroll
        for (int o = 1; o < 32; o <<= 1) {
            int u = __shfl_up_sync(0xffffffffu, y, o);
            if (lane >= o) y += u;
        }
        ws[lane] = y;
    }
    __syncthreads();
    int excl = x - s + (w > 0 ? ws[w - 1] : 0) + g_blksum[b];
    if (i < NN) { g_off[i] = excl; g_cur[i] = excl; }
    if (i + 1 < NN) { g_off[i + 1] = excl + v0; g_cur[i + 1] = excl + v0; }
}

__global__ void k_fill(const int* __restrict__ ei) {
    int i = blockIdx.x * blockDim.x + threadIdx.x;
    if (i >= ET) return;
    int src = (i < EE) ? ei[i] : (i - EE);
    int dst = (i < EE) ? ei[EE + i] : (i - EE);
    int p = atomicAdd(&g_cur[dst], 1);
    g_csrc[p] = src;
}

// ---------------- bf16 3-pass mma.sync GEMM with in-register A split ----------------
// C tile (128x128) = (Ah+Al)[M,K] @ (Bh+Bl)^T.  A is fp32 [M,K], split on the fly
// (optionally BN-normalized first). Bh/Bl: pre-split bf16 [Ntot][K].
// 8 warps, 32x64 warp tiles, K chunks of 32, double-buffered (A via reg prefetch,
// B via cp.async). smem buffer: Ah | Al | Bh | Bl, 128 rows x 32 halves, stride 80B.
template <int K, bool NORM>
__global__ void __launch_bounds__(256, 1) k_mma(
    const float* __restrict__ A,
    const __nv_bfloat16* __restrict__ Bh, const __nv_bfloat16* __restrict__ Bl,
    float* __restrict__ C, int ldc, int M) {
    extern __shared__ __align__(128) char smem[];
    constexpr int NC = K / 32;
    const int tid = threadIdx.x, lane = tid & 31, wid = tid >> 5;
    const int row0 = blockIdx.y * 128, n0 = blockIdx.x * 128;
    const int wm = (wid & 3) * 32, wn = (wid >> 2) * 64;
    const uint32_t sb = smem_u32(smem);
    float* sScale = (float*)(smem + 81920);
    float* sShift = (float*)(smem + 81920 + 1024);

    if (NORM) {
        if (tid < K) { sScale[tid] = g_scale[tid]; sShift[tid] = g_shift[tid]; }
        __syncthreads();
    }

    float c[2][8][4];
#pragma unroll
    for (int mf = 0; mf < 2; mf++)
#pragma unroll
        for (int nf = 0; nf < 8; nf++)
#pragma unroll
            for (int q = 0; q < 4; q++) c[mf][nf][q] = 0.f;

    const int ar = tid >> 1;             // A row within tile
    const int ac = (tid & 1) * 16;       // A col-seg within chunk
    const int agr = min(row0 + ar, M - 1);

    auto ldgA = [&](int ch, float* f) {
        const float* ap = A + (size_t)agr * K + ch * 32 + ac;
#pragma unroll
        for (int q = 0; q < 4; q++) {
            float4 v = *(const float4*)(ap + q * 4);
            f[q * 4 + 0] = v.x; f[q * 4 + 1] = v.y;
            f[q * 4 + 2] = v.z; f[q * 4 + 3] = v.w;
        }
    };
    auto stsA = [&](int ch, float* f) {
        const uint32_t base = sb + (uint32_t)(ch & 1) * 40960u;
        if (NORM) {
            const int c0 = ch * 32 + ac;
#pragma unroll
            for (int i = 0; i < 16; i++) f[i] = fmaf(f[i], sScale[c0 + i], sShift[c0 + i]);
        }
        float h[16], l[16];
#pragma unroll
        for (int i = 0; i < 16; i++) {
            __nv_bfloat16 hb = __float2bfloat16(f[i]);
            h[i] = __bfloat162float(hb);
            l[i] = f[i] - h[i];
        }
        const uint32_t ad = base + (uint32_t)ar * 80u + (uint32_t)ac * 2u;
        uint4 H0 = make_uint4(pk2(h[0], h[1]), pk2(h[2], h[3]), pk2(h[4], h[5]), pk2(h[6], h[7]));
        uint4 H1 = make_uint4(pk2(h[8], h[9]), pk2(h[10], h[11]), pk2(h[12], h[13]), pk2(h[14], h[15]));
        uint4 L0 = make_uint4(pk2(l[0], l[1]), pk2(l[2], l[3]), pk2(l[4], l[5]), pk2(l[6], l[7]));
        uint4 L1 = make_uint4(pk2(l[8], l[9]), pk2(l[10], l[11]), pk2(l[12], l[13]), pk2(l[14], l[15]));
        *(uint4*)(smem + (ad - sb)) = H0;
        *(uint4*)(smem + (ad - sb) + 16) = H1;
        *(uint4*)(smem + (ad - sb) + 10240) = L0;
        *(uint4*)(smem + (ad - sb) + 10240 + 16) = L1;
    };
    auto issueB = [&](int ch) {
        const int k0 = ch * 32;
        const uint32_t base = sb + (uint32_t)(ch & 1) * 40960u + 20480u;
#pragma unroll
        for (int j = 0; j < 2; j++) {
            int seg = tid + 256 * j;
            int r = seg >> 2, s = seg & 3;
            const void* srch = Bh + (size_t)(n0 + r) * K + k0 + s * 8;
            const void* srcl = Bl + (size_t)(n0 + r) * K + k0 + s * 8;
            uint32_t dst = base + (uint32_t)r * 80u + (uint32_t)s * 16u;
            CP_ASYNC16(dst, srch);
            CP_ASYNC16(dst + 10240u, srcl);
        }
    };

    // prologue
    float areg[16];
    ldgA(0, areg);
    stsA(0, areg);
    issueB(0);
    CP_COMMIT();
    if (NC > 1) {
        issueB(1);
        CP_COMMIT();
        ldgA(1, areg);
    }

    // ldmatrix per-lane address pieces
    const int grp = lane >> 3, r8 = lane & 7;
    const uint32_t a_row = (uint32_t)(((grp & 1) ? 8 : 0) + r8);
    const uint32_t a_k16 = (grp & 2) ? 16u : 0u;
    const uint32_t b_row = (uint32_t)(((grp & 2) ? 8 : 0) + r8);
    const uint32_t b_k16 = (grp & 1) ? 16u : 0u;

    for (int ch = 0; ch < NC; ch++) {
        if (ch + 1 < NC) { CP_WAIT(1); } else { CP_WAIT(0); }
        __syncthreads();
        const uint32_t sA = sb + (uint32_t)(ch & 1) * 40960u;
#pragma unroll
        for (int ks = 0; ks < 2; ks++) {
            const uint32_t ko = (uint32_t)ks * 32u;
            uint32_t ah[2][4], al[2][4], bh[4][4], bl[4][4];
#pragma unroll
            for (int mf = 0; mf < 2; mf++) {
                uint32_t addr = sA + ((uint32_t)(wm + mf * 16) + a_row) * 80u + ko + a_k16;
                LDM_X4(ah[mf][0], ah[mf][1], ah[mf][2], ah[mf][3], addr);
                LDM_X4(al[mf][0], al[mf][1], al[mf][2], al[mf][3], addr + 10240u);
            }
#pragma unroll
            for (int pf = 0; pf < 4; pf++) {
                uint32_t addr = sA + 20480u + ((uint32_t)(wn + pf * 16) + b_row) * 80u + ko + b_k16;
                LDM_X4(bh[pf][0], bh[pf][1], bh[pf][2], bh[pf][3], addr);
                LDM_X4(bl[pf][0], bl[pf][1], bl[pf][2], bl[pf][3], addr + 10240u);
            }
#pragma unroll
            for (int mf = 0; mf < 2; mf++)
#pragma unroll
                for (int nf = 0; nf < 8; nf++) {
                    const int pf = nf >> 1, h = (nf & 1) * 2;
                    MMA_BF16(c[mf][nf], ah[mf], bh[pf][h], bh[pf][h + 1]);
                    MMA_BF16(c[mf][nf], ah[mf], bl[pf][h], bl[pf][h + 1]);
                    MMA_BF16(c[mf][nf], al[mf], bh[pf][h], bh[pf][h + 1]);
                }
        }
        if (ch + 1 < NC) {
            stsA(ch + 1, areg);               // other buffer: safe pre-sync
            if (ch + 2 < NC) ldgA(ch + 2, areg);
        }
        __syncthreads();
        if (ch + 2 < NC) {
            issueB(ch + 2);                    // reuses buffer (ch&1): safe post-sync
            CP_COMMIT();
        }
    }

    // epilogue
    const int g = lane >> 2, tg = lane & 3;
#pragma unroll
    for (int mf = 0; mf < 2; mf++) {
        int row = row0 + wm + mf * 16 + g;
#pragma unroll
        for (int nf = 0; nf < 8; nf++) {
            int col = n0 + wn + nf * 8 + 2 * tg;
            if (row < M)
                *(float2*)(C + (size_t)row * ldc + col) = make_float2(c[mf][nf][0], c[mf][nf][1]);
            if (row + 8 < M)
                *(float2*)(C + (size_t)(row + 8) * ldc + col) = make_float2(c[mf][nf][2], c[mf][nf][3]);
        }
    }
}

// ---------------- GATv2 aggregation: warp per dst node, online softmax ----------------
template <int HEADS, bool FINAL>
__global__ void k_agg(const float* __restrict__ y,      // [NN, 2*CH]  = [xl | xr]
                      const float* __restrict__ att,    // [CH]
                      const float* __restrict__ bias,   // [CH]
                      float* __restrict__ hout,         // [NN, CH]  (if !FINAL)
                      const int* __restrict__ batch) {
    constexpr int CH = HEADS * 128;
    constexpr int R = CH / 32;
    constexpr int HR = R / HEADS;
    const int lane = threadIdx.x & 31;
    const int t = (blockIdx.x * blockDim.x + threadIdx.x) >> 5;
    if (t >= NN) return;

    const float* yt = y + (size_t)t * (2 * CH) + CH;  // xr[t]
    float xr[R], attv[R], acc[R];
#pragma unroll
    for (int r = 0; r < R; r++) {
        int c = lane + 32 * r;
        xr[r] = yt[c];
        attv[r] = att[c];
        acc[r] = 0.f;
    }
    float emax[HEADS], den[HEADS];
#pragma unroll
    for (int h = 0; h < HEADS; h++) { emax[h] = -1e30f; den[h] = 0.f; }

    const int s0 = g_off[t], s1 = g_off[t + 1];
#pragma unroll 2
    for (int j = s0; j < s1; j++) {
        int s = g_csrc[j];
        const float* ys = y + (size_t)s * (2 * CH);  // xl[s]
        float xv[R], d[HEADS];
#pragma unroll
        for (int h = 0; h < HEADS; h++) d[h] = 0.f;
#pragma unroll
        for (int r = 0; r < R; r++) {
            float v = ys[lane + 32 * r];
            xv[r] = v;
            float m = v + xr[r];
            m = (m > 0.f) ? m : 0.2f * m;  // leaky relu
            d[r / HR] = fmaf(m, attv[r], d[r / HR]);
        }
#pragma unroll
        for (int h = 0; h < HEADS; h++) {
#pragma unroll
            for (int o = 16; o; o >>= 1) d[h] += __shfl_xor_sync(0xffffffffu, d[h], o);
        }
        float ex[HEADS];
#pragma unroll
        for (int h = 0; h < HEADS; h++) {
            if (d[h] > emax[h]) {
                float corr = __expf(emax[h] - d[h]);
                den[h] *= corr;
#pragma unroll
                for (int r = h * HR; r < (h + 1) * HR; r++) acc[r] *= corr;
                emax[h] = d[h];
                ex[h] = 1.f;
            } else {
                ex[h] = __expf(d[h] - emax[h]);
            }
            den[h] += ex[h];
        }
#pragma unroll
        for (int r = 0; r < R; r++) acc[r] = fmaf(ex[r / HR], xv[r], acc[r]);
    }

    if (FINAL) {
        int g = batch[t];
#pragma unroll
        for (int r = 0; r < R; r++) {
            int c = lane + 32 * r;
            float v = acc[r] / (den[r / HR] + 1e-16f) + bias[c];
            atomicAdd(&g_pool[g * CH + c], v);
        }
        if (lane == 0) atomicAdd(&g_cnt[g], 1.f);
    } else {
#pragma unroll
        for (int r = 0; r < R; r++) {
            int c = lane + 32 * r;
            float v = acc[r] / (den[r / HR] + 1e-16f) + bias[c];
            v = (v > 0.f) ? v : expm1f(v);  // ELU
            hout[(size_t)t * CH + c] = v;
        }
    }
}

// ---------------- BatchNorm stats + finalize ----------------
__global__ void k_bnstats(const float* __restrict__ h) {
    int c = threadIdx.x;  // 256
    float s = 0.f, q = 0.f;
    for (int r = blockIdx.x; r < NN; r += gridDim.x) {
        float v = h[(size_t)r * 256 + c];
        s += v;
        q = fmaf(v, v, q);
    }
    atomicAdd(&g_bnsum[c], (double)s);
    atomicAdd(&g_bnsq[c], (double)q);
}

__global__ void k_bnfin(const float* __restrict__ gamma, const float* __restrict__ beta) {
    int c = threadIdx.x;  // 256
    float mu = (float)(g_bnsum[c] / (double)NN);
    float var = (float)(g_bnsq[c] / (double)NN) - mu * mu;
    float sc = gamma[c] * rsqrtf(var + 1e-5f);
    g_scale[c] = sc;
    g_shift[c] = beta[c] - mu * sc;
}

// ---------------- final: pooled mean @ Wlin + blin ----------------
__global__ void k_final(const float* __restrict__ Wlin, const float* __restrict__ blin,
                        float* __restrict__ out) {
    int g = blockIdx.x;        // GG blocks
    int t = threadIdx.x;       // 128 threads
    float inv = 1.f / fmaxf(g_cnt[g], 1.f);
    float p = g_pool[g * 128 + t] * inv;
    float a0 = p * Wlin[2 * t + 0];
    float a1 = p * Wlin[2 * t + 1];
#pragma unroll
    for (int o = 16; o; o >>= 1) {
        a0 += __shfl_xor_sync(0xffffffffu, a0, o);
        a1 += __shfl_xor_sync(0xffffffffu, a1, o);
    }
    __shared__ float sa[4], sb2[4];
    if ((t & 31) == 0) { sa[t >> 5] = a0; sb2[t >> 5] = a1; }
    __syncthreads();
    if (t == 0) out[2 * g + 0] = sa[0] + sa[1] + sa[2] + sa[3] + blin[0];
    if (t == 1) out[2 * g + 1] = sb2[0] + sb2[1] + sb2[2] + sb2[3] + blin[1];
}

// ---------------- launcher ----------------
extern "C" void kernel_launch(void* const* d_in, const int* in_sizes, int n_in,
                              void* d_out, int out_size) {
    const float* x     = (const float*)d_in[0];
    const int*   ei    = (const int*)d_in[1];
    const int*   batch = (const int*)d_in[2];
    const float* Wl1   = (const float*)d_in[3];
    const float* Wr1   = (const float*)d_in[4];
    const float* att1  = (const float*)d_in[5];
    const float* b1    = (const float*)d_in[6];
    const float* gamma = (const float*)d_in[7];
    const float* beta  = (const float*)d_in[8];
    const float* Wl2   = (const float*)d_in[9];
    const float* Wr2   = (const float*)d_in[10];
    const float* att2  = (const float*)d_in[11];
    const float* b2    = (const float*)d_in[12];
    const float* Wlin  = (const float*)d_in[13];
    const float* blin  = (const float*)d_in[14];
    float* out = (float*)d_out;

    void *p_y1, *p_h1, *p_y2, *p_b1h, *p_b1l, *p_b2h, *p_b2l;
    cudaGetSymbolAddress(&p_y1, g_y1);
    cudaGetSymbolAddress(&p_h1, g_h1);
    cudaGetSymbolAddress(&p_y2, g_y2);
    cudaGetSymbolAddress(&p_b1h, g_B1h);
    cudaGetSymbolAddress(&p_b1l, g_B1l);
    cudaGetSymbolAddress(&p_b2h, g_B2h);
    cudaGetSymbolAddress(&p_b2l, g_B2l);
    float* y1 = (float*)p_y1;
    float* h1 = (float*)p_h1;
    float* y2 = (float*)p_y2;

    const int SMEMSZ = 81920 + 2048;  // 2 pipeline buffers + BN scale/shift
    cudaFuncSetAttribute(k_mma<128, false>, cudaFuncAttributeMaxDynamicSharedMemorySize, SMEMSZ);
    cudaFuncSetAttribute(k_mma<256, true>, cudaFuncAttributeMaxDynamicSharedMemorySize, SMEMSZ);

    // CSR build + weight split
    k_init<<<256, 256>>>();
    k_splitB<<<512, 256>>>(Wl1, Wr1, Wl2, Wr2);
    k_hist<<<(ET + 255) / 256, 256>>>(ei);
    k_scanA<<<SCB, 1024>>>();
    k_scanB<<<1, 32>>>();
    k_scanC<<<SCB, 1024>>>();
    k_fill<<<(ET + 255) / 256, 256>>>(ei);

    const int MB = (NN + 127) / 128;  // 391

    // Layer 1: y1 = x @ [Wl1 | Wr1]   (bf16 3-pass mma.sync, in-reg A split)
    k_mma<128, false><<<dim3(4, MB), 256, SMEMSZ>>>(
        x, (const __nv_bfloat16*)p_b1h, (const __nv_bfloat16*)p_b1l, y1, 512, NN);
    k_agg<2, false><<<(NN * 32 + 255) / 256, 256>>>(y1, att1, b1, h1, nullptr);

    // BatchNorm stats -> affine folded into layer-2 GEMM A-loads
    k_bnstats<<<512, 256>>>(h1);
    k_bnfin<<<1, 256>>>(gamma, beta);

    // Layer 2: y2 = bn(h1) @ [Wl2 | Wr2]
    k_mma<256, true><<<dim3(2, MB), 256, SMEMSZ>>>(
        h1, (const __nv_bfloat16*)p_b2h, (const __nv_bfloat16*)p_b2l, y2, 256, NN);
    k_agg<1, true><<<(NN * 32 + 255) / 256, 256>>>(y2, att2, b2, nullptr, batch);

    // Pool mean + final linear
    k_final<<<GG, 128>>>(Wlin, blin, out);
}

// round 8
// speedup vs baseline: 1.5572x; 1.0145x over previous
#include <cuda_runtime.h>
#include <cuda_bf16.h>
#include <math.h>
#include <stdint.h>

#define NN 50000
#define EE 800000
#define ET 850000   // EE + NN self loops
#define GG 512
#define SCB 25      // scan blocks (2048 elems each)

// ---------------- static scratch (no allocations allowed) ----------------
__device__ __align__(128) float g_y1[(size_t)NN * 512];  // [xl1 | xr1]
__device__ __align__(128) float g_h1[(size_t)NN * 256];  // post-ELU layer1 output
__device__ __align__(128) float g_y2[(size_t)NN * 256];  // [xl2 | xr2]
__device__ __align__(128) __nv_bfloat16 g_B1h[512 * 128];  // layer1 B^T hi [n][k]
__device__ __align__(128) __nv_bfloat16 g_B1l[512 * 128];
__device__ __align__(128) __nv_bfloat16 g_B2h[256 * 256];  // layer2 B^T hi [n][k]
__device__ __align__(128) __nv_bfloat16 g_B2l[256 * 256];
__device__ int    g_deg[NN];
__device__ int    g_off[NN + 1];
__device__ int    g_cur[NN];
__device__ int    g_csrc[ET];
__device__ int    g_blksum[32];
__device__ double g_bnsum[256];
__device__ double g_bnsq[256];
__device__ float  g_scale[256];
__device__ float  g_shift[256];
__device__ float  g_pool[GG * 128];
__device__ float  g_cnt[GG];

// ---------------- PTX helpers (baseline sm_80/sm_90 features only) ----------------
__device__ __forceinline__ uint32_t smem_u32(const void* p) {
    uint32_t r;
    asm("{ .reg .u64 t; cvta.to.shared.u64 t, %1; cvt.u32.u64 %0, t; }" : "=r"(r) : "l"(p));
    return r;
}
#define CP_ASYNC16(dst, src) \
    asm volatile("cp.async.cg.shared.global [%0], [%1], 16;" :: "r"(dst), "l"(src) : "memory")
#define CP_COMMIT() asm volatile("cp.async.commit_group;" ::: "memory")
#define CP_WAIT(n)  asm volatile("cp.async.wait_group %0;" :: "n"(n) : "memory")
#define LDM_X4(r0, r1, r2, r3, addr) \
    asm volatile("ldmatrix.sync.aligned.m8n8.x4.shared.b16 {%0,%1,%2,%3}, [%4];" \
        : "=r"(r0), "=r"(r1), "=r"(r2), "=r"(r3) : "r"(addr))
#define MMA_BF16(cc, a, b0v, b1v) \
    asm volatile("mma.sync.aligned.m16n8k16.row.col.f32.bf16.bf16.f32 " \
        "{%0,%1,%2,%3}, {%4,%5,%6,%7}, {%8,%9}, {%0,%1,%2,%3};" \
        : "+f"((cc)[0]), "+f"((cc)[1]), "+f"((cc)[2]), "+f"((cc)[3]) \
        : "r"((a)[0]), "r"((a)[1]), "r"((a)[2]), "r"((a)[3]), "r"(b0v), "r"(b1v))

__device__ __forceinline__ void split_bf16(float v, __nv_bfloat16& h, __nv_bfloat16& l) {
    h = __float2bfloat16(v);
    l = __float2bfloat16(v - __bfloat162float(h));
}
__device__ __forceinline__ uint32_t pk2(float a, float b) {
    __nv_bfloat162 t = __floats2bfloat162_rn(a, b);
    return *reinterpret_cast<uint32_t*>(&t);
}

// ---------------- init ----------------
__global__ void k_initMain() {
    int i = blockIdx.x * blockDim.x + threadIdx.x;  // 65536 threads
    if (i < GG * 128) g_pool[i] = 0.f;
    if (i < GG) g_cnt[i] = 0.f;
    if (i < 256) { g_bnsum[i] = 0.0; g_bnsq[i] = 0.0; }
}

__global__ void k_initDeg() {
    int i = blockIdx.x * blockDim.x + threadIdx.x;
    if (i < NN) g_deg[i] = 0;
}

// ---------------- pre-split & transpose weights (hi/lo bf16) ----------------
__global__ void k_splitB(const float* __restrict__ Wl1, const float* __restrict__ Wr1,
                         const float* __restrict__ Wl2, const float* __restrict__ Wr2) {
    int i = blockIdx.x * blockDim.x + threadIdx.x;  // 131072 threads
    if (i < 512 * 128) {
        int n = i >> 7, k = i & 127;
        float w = (n < 256) ? Wl1[k * 256 + n] : Wr1[k * 256 + (n - 256)];
        split_bf16(w, g_B1h[i], g_B1l[i]);
    } else if (i < 512 * 128 + 256 * 256) {
        int j = i - 512 * 128;
        int n = j >> 8, k = j & 255;
        float w = (n < 128) ? Wl2[k * 128 + n] : Wr2[k * 128 + (n - 128)];
        split_bf16(w, g_B2h[j], g_B2l[j]);
    }
}

// ---------------- CSR build ----------------
__global__ void k_hist(const int* __restrict__ ei) {
    int i = blockIdx.x * blockDim.x + threadIdx.x;
    if (i >= ET) return;
    int dst = (i < EE) ? ei[EE + i] : (i - EE);
    atomicAdd(&g_deg[dst], 1);
}

// hierarchical scan: A) block sums, B) scan block sums, C) full scan + write
__global__ void k_scanA() {  // grid SCB, block 1024
    __shared__ int ws[32];
    const int b = blockIdx.x, t = threadIdx.x;
    const int i = b * 2048 + 2 * t;
    int v0 = 0, v1 = 0;
    if (i + 1 < NN) { int2 p = *(const int2*)&g_deg[i]; v0 = p.x; v1 = p.y; }
    else if (i < NN) v0 = g_deg[i];
    int s = v0 + v1;
#pragma unroll
    for (int o = 16; o; o >>= 1) s += __shfl_xor_sync(0xffffffffu, s, o);
    if ((t & 31) == 0) ws[t >> 5] = s;
    __syncthreads();
    if (t < 32) {
        int x = ws[t];
#pragma unroll
        for (int o = 16; o; o >>= 1) x += __shfl_xor_sync(0xffffffffu, x, o);
        if (t == 0) g_blksum[b] = x;
    }
}

__global__ void k_scanB() {  // 1 block, 32 threads: exclusive scan of SCB sums
    int t = threadIdx.x;
    int v = (t < SCB) ? g_blksum[t] : 0;
    int x = v;
#pragma unroll
    for (int o = 1; o < 32; o <<= 1) {
        int u = __shfl_up_sync(0xffffffffu, x, o);
        if (t >= o) x += u;
    }
    if (t < SCB) g_blksum[t] = x - v;  // exclusive
    if (t == SCB - 1) g_off[NN] = x;   // grand total
}

__global__ void k_scanC() {  // grid SCB, block 1024: full scan + write off/cur
    __shared__ int ws[32];
    const int b = blockIdx.x, t = threadIdx.x;
    const int lane = t & 31, w = t >> 5;
    const int i = b * 2048 + 2 * t;
    int v0 = 0, v1 = 0;
    if (i + 1 < NN) { int2 p = *(const int2*)&g_deg[i]; v0 = p.x; v1 = p.y; }
    else if (i < NN) v0 = g_deg[i];
    int s = v0 + v1;
    int x = s;
#pragma unroll
    for (int o = 1; o < 32; o <<= 1) {
        int u = __shfl_up_sync(0xffffffffu, x, o);
        if (lane >= o) x += u;
    }
    if (lane == 31) ws[w] = x;
    __syncthreads();
    if (w == 0) {
        int y = ws[lane];
#pragma unroll
        for (int o = 1; o < 32; o <<= 1) {
            int u = __shfl_up_sync(0xffffffffu, y, o);
            if (lane >= o) y += u;
        }
        ws[lane] = y;
    }
    __syncthreads();
    int excl = x - s + (w > 0 ? ws[w - 1] : 0) + g_blksum[b];
    if (i < NN) { g_off[i] = excl; g_cur[i] = excl; }
    if (i + 1 < NN) { g_off[i + 1] = excl + v0; g_cur[i + 1] = excl + v0; }
}

__global__ void k_fill(const int* __restrict__ ei) {
    int i = blockIdx.x * blockDim.x + threadIdx.x;
    if (i >= ET) return;
    int src = (i < EE) ? ei[i] : (i - EE);
    int dst = (i < EE) ? ei[EE + i] : (i - EE);
    int p = atomicAdd(&g_cur[dst], 1);
    g_csrc[p] = src;
}

// ---------------- bf16 3-pass mma.sync GEMM with in-register A split ----------------
// C tile (128x128) = (Ah+Al)[M,K] @ (Bh+Bl)^T.  A is fp32 [M,K], split on the fly
// (optionally BN-normalized first). Bh/Bl: pre-split bf16 [Ntot][K].
// 8 warps, 32x64 warp tiles, K chunks of 32, double-buffered (A via reg prefetch,
// B via cp.async). smem buffer: Ah | Al | Bh | Bl, 128 rows x 32 halves, stride 80B.
template <int K, bool NORM>
__global__ void __launch_bounds__(256, 1) k_mma(
    const float* __restrict__ A,
    const __nv_bfloat16* __restrict__ Bh, const __nv_bfloat16* __restrict__ Bl,
    float* __restrict__ C, int ldc, int M) {
    extern __shared__ __align__(128) char smem[];
    constexpr int NC = K / 32;
    const int tid = threadIdx.x, lane = tid & 31, wid = tid >> 5;
    const int row0 = blockIdx.y * 128, n0 = blockIdx.x * 128;
    const int wm = (wid & 3) * 32, wn = (wid >> 2) * 64;
    const uint32_t sb = smem_u32(smem);
    float* sScale = (float*)(smem + 81920);
    float* sShift = (float*)(smem + 81920 + 1024);

    if (NORM) {
        if (tid < K) { sScale[tid] = g_scale[tid]; sShift[tid] = g_shift[tid]; }
        __syncthreads();
    }

    float c[2][8][4];
#pragma unroll
    for (int mf = 0; mf < 2; mf++)
#pragma unroll
        for (int nf = 0; nf < 8; nf++)
#pragma unroll
            for (int q = 0; q < 4; q++) c[mf][nf][q] = 0.f;

    const int ar = tid >> 1;             // A row within tile
    const int ac = (tid & 1) * 16;       // A col-seg within chunk
    const int agr = min(row0 + ar, M - 1);

    auto ldgA = [&](int ch, float* f) {
        const float* ap = A + (size_t)agr * K + ch * 32 + ac;
#pragma unroll
        for (int q = 0; q < 4; q++) {
            float4 v = *(const float4*)(ap + q * 4);
            f[q * 4 + 0] = v.x; f[q * 4 + 1] = v.y;
            f[q * 4 + 2] = v.z; f[q * 4 + 3] = v.w;
        }
    };
    auto stsA = [&](int ch, float* f) {
        const uint32_t base = sb + (uint32_t)(ch & 1) * 40960u;
        if (NORM) {
            const int c0 = ch * 32 + ac;
#pragma unroll
            for (int i = 0; i < 16; i++) f[i] = fmaf(f[i], sScale[c0 + i], sShift[c0 + i]);
        }
        float h[16], l[16];
#pragma unroll
        for (int i = 0; i < 16; i++) {
            __nv_bfloat16 hb = __float2bfloat16(f[i]);
            h[i] = __bfloat162float(hb);
            l[i] = f[i] - h[i];
        }
        const uint32_t ad = base + (uint32_t)ar * 80u + (uint32_t)ac * 2u;
        uint4 H0 = make_uint4(pk2(h[0], h[1]), pk2(h[2], h[3]), pk2(h[4], h[5]), pk2(h[6], h[7]));
        uint4 H1 = make_uint4(pk2(h[8], h[9]), pk2(h[10], h[11]), pk2(h[12], h[13]), pk2(h[14], h[15]));
        uint4 L0 = make_uint4(pk2(l[0], l[1]), pk2(l[2], l[3]), pk2(l[4], l[5]), pk2(l[6], l[7]));
        uint4 L1 = make_uint4(pk2(l[8], l[9]), pk2(l[10], l[11]), pk2(l[12], l[13]), pk2(l[14], l[15]));
        *(uint4*)(smem + (ad - sb)) = H0;
        *(uint4*)(smem + (ad - sb) + 16) = H1;
        *(uint4*)(smem + (ad - sb) + 10240) = L0;
        *(uint4*)(smem + (ad - sb) + 10240 + 16) = L1;
    };
    auto issueB = [&](int ch) {
        const int k0 = ch * 32;
        const uint32_t base = sb + (uint32_t)(ch & 1) * 40960u + 20480u;
#pragma unroll
        for (int j = 0; j < 2; j++) {
            int seg = tid + 256 * j;
            int r = seg >> 2, s = seg & 3;
            const void* srch = Bh + (size_t)(n0 + r) * K + k0 + s * 8;
            const void* srcl = Bl + (size_t)(n0 + r) * K + k0 + s * 8;
            uint32_t dst = base + (uint32_t)r * 80u + (uint32_t)s * 16u;
            CP_ASYNC16(dst, srch);
            CP_ASYNC16(dst + 10240u, srcl);
        }
    };

    // prologue
    float areg[16];
    ldgA(0, areg);
    stsA(0, areg);
    issueB(0);
    CP_COMMIT();
    if (NC > 1) {
        issueB(1);
        CP_COMMIT();
        ldgA(1, areg);
    }

    // ldmatrix per-lane address pieces
    const int grp = lane >> 3, r8 = lane & 7;
    const uint32_t a_row = (uint32_t)(((grp & 1) ? 8 : 0) + r8);
    const uint32_t a_k16 = (grp & 2) ? 16u : 0u;
    const uint32_t b_row = (uint32_t)(((grp & 2) ? 8 : 0) + r8);
    const uint32_t b_k16 = (grp & 1) ? 16u : 0u;

    for (int ch = 0; ch < NC; ch++) {
        if (ch + 1 < NC) { CP_WAIT(1); } else { CP_WAIT(0); }
        __syncthreads();
        const uint32_t sA = sb + (uint32_t)(ch & 1) * 40960u;
#pragma unroll
        for (int ks = 0; ks < 2; ks++) {
            const uint32_t ko = (uint32_t)ks * 32u;
            uint32_t ah[2][4], al[2][4], bh[4][4], bl[4][4];
#pragma unroll
            for (int mf = 0; mf < 2; mf++) {
                uint32_t addr = sA + ((uint32_t)(wm + mf * 16) + a_row) * 80u + ko + a_k16;
                LDM_X4(ah[mf][0], ah[mf][1], ah[mf][2], ah[mf][3], addr);
                LDM_X4(al[mf][0], al[mf][1], al[mf][2], al[mf][3], addr + 10240u);
            }
#pragma unroll
            for (int pf = 0; pf < 4; pf++) {
                uint32_t addr = sA + 20480u + ((uint32_t)(wn + pf * 16) + b_row) * 80u + ko + b_k16;
                LDM_X4(bh[pf][0], bh[pf][1], bh[pf][2], bh[pf][3], addr);
                LDM_X4(bl[pf][0], bl[pf][1], bl[pf][2], bl[pf][3], addr + 10240u);
            }
#pragma unroll
            for (int mf = 0; mf < 2; mf++)
#pragma unroll
                for (int nf = 0; nf < 8; nf++) {
                    const int pf = nf >> 1, h = (nf & 1) * 2;
                    MMA_BF16(c[mf][nf], ah[mf], bh[pf][h], bh[pf][h + 1]);
                    MMA_BF16(c[mf][nf], ah[mf], bl[pf][h], bl[pf][h + 1]);
                    MMA_BF16(c[mf][nf], al[mf], bh[pf][h], bh[pf][h + 1]);
                }
        }
        if (ch + 1 < NC) {
            stsA(ch + 1, areg);               // other buffer: safe pre-sync
            if (ch + 2 < NC) ldgA(ch + 2, areg);
        }
        __syncthreads();
        if (ch + 2 < NC) {
            issueB(ch + 2);                    // reuses buffer (ch&1): safe post-sync
            CP_COMMIT();
        }
    }

    // epilogue
    const int g = lane >> 2, tg = lane & 3;
#pragma unroll
    for (int mf = 0; mf < 2; mf++) {
        int row = row0 + wm + mf * 16 + g;
#pragma unroll
        for (int nf = 0; nf < 8; nf++) {
            int col = n0 + wn + nf * 8 + 2 * tg;
            if (row < M)
                *(float2*)(C + (size_t)row * ldc + col) = make_float2(c[mf][nf][0], c[mf][nf][1]);
            if (row + 8 < M)
                *(float2*)(C + (size_t)(row + 8) * ldc + col) = make_float2(c[mf][nf][2], c[mf][nf][3]);
        }
    }
}

// ---------------- GATv2 aggregation: warp per dst node, online softmax ----------------
template <int HEADS, bool FINAL>
__global__ void k_agg(const float* __restrict__ y,      // [NN, 2*CH]  = [xl | xr]
                      const float* __restrict__ att,    // [CH]
                      const float* __restrict__ bias,   // [CH]
                      float* __restrict__ hout,         // [NN, CH]  (if !FINAL)
                      const int* __restrict__ batch) {
    constexpr int CH = HEADS * 128;
    constexpr int R = CH / 32;
    constexpr int HR = R / HEADS;
    const int lane = threadIdx.x & 31;
    const int t = (blockIdx.x * blockDim.x + threadIdx.x) >> 5;
    if (t >= NN) return;

    const float* yt = y + (size_t)t * (2 * CH) + CH;  // xr[t]
    float xr[R], attv[R], acc[R];
#pragma unroll
    for (int r = 0; r < R; r++) {
        int c = lane + 32 * r;
        xr[r] = yt[c];
        attv[r] = att[c];
        acc[r] = 0.f;
    }
    float emax[HEADS], den[HEADS];
#pragma unroll
    for (int h = 0; h < HEADS; h++) { emax[h] = -1e30f; den[h] = 0.f; }

    const int s0 = g_off[t], s1 = g_off[t + 1];
#pragma unroll 2
    for (int j = s0; j < s1; j++) {
        int s = g_csrc[j];
        const float* ys = y + (size_t)s * (2 * CH);  // xl[s]
        float xv[R], d[HEADS];
#pragma unroll
        for (int h = 0; h < HEADS; h++) d[h] = 0.f;
#pragma unroll
        for (int r = 0; r < R; r++) {
            float v = ys[lane + 32 * r];
            xv[r] = v;
            float m = v + xr[r];
            m = (m > 0.f) ? m : 0.2f * m;  // leaky relu
            d[r / HR] = fmaf(m, attv[r], d[r / HR]);
        }
#pragma unroll
        for (int h = 0; h < HEADS; h++) {
#pragma unroll
            for (int o = 16; o; o >>= 1) d[h] += __shfl_xor_sync(0xffffffffu, d[h], o);
        }
        float ex[HEADS];
#pragma unroll
        for (int h = 0; h < HEADS; h++) {
            if (d[h] > emax[h]) {
                float corr = __expf(emax[h] - d[h]);
                den[h] *= corr;
#pragma unroll
                for (int r = h * HR; r < (h + 1) * HR; r++) acc[r] *= corr;
                emax[h] = d[h];
                ex[h] = 1.f;
            } else {
                ex[h] = __expf(d[h] - emax[h]);
            }
            den[h] += ex[h];
        }
#pragma unroll
        for (int r = 0; r < R; r++) acc[r] = fmaf(ex[r / HR], xv[r], acc[r]);
    }

    if (FINAL) {
        int g = batch[t];
#pragma unroll
        for (int r = 0; r < R; r++) {
            int c = lane + 32 * r;
            float v = acc[r] / (den[r / HR] + 1e-16f) + bias[c];
            atomicAdd(&g_pool[g * CH + c], v);
        }
        if (lane == 0) atomicAdd(&g_cnt[g], 1.f);
    } else {
#pragma unroll
        for (int r = 0; r < R; r++) {
            int c = lane + 32 * r;
            float v = acc[r] / (den[r / HR] + 1e-16f) + bias[c];
            v = (v > 0.f) ? v : expm1f(v);  // ELU
            hout[(size_t)t * CH + c] = v;
        }
    }
}

// ---------------- BatchNorm stats + finalize ----------------
__global__ void k_bnstats(const float* __restrict__ h) {
    int c = threadIdx.x;  // 256
    float s = 0.f, q = 0.f;
    for (int r = blockIdx.x; r < NN; r += gridDim.x) {
        float v = h[(size_t)r * 256 + c];
        s += v;
        q = fmaf(v, v, q);
    }
    atomicAdd(&g_bnsum[c], (double)s);
    atomicAdd(&g_bnsq[c], (double)q);
}

__global__ void k_bnfin(const float* __restrict__ gamma, const float* __restrict__ beta) {
    int c = threadIdx.x;  // 256
    float mu = (float)(g_bnsum[c] / (double)NN);
    float var = (float)(g_bnsq[c] / (double)NN) - mu * mu;
    float sc = gamma[c] * rsqrtf(var + 1e-5f);
    g_scale[c] = sc;
    g_shift[c] = beta[c] - mu * sc;
}

// ---------------- final: pooled mean @ Wlin + blin ----------------
__global__ void k_final(const float* __restrict__ Wlin, const float* __restrict__ blin,
                        float* __restrict__ out) {
    int g = blockIdx.x;        // GG blocks
    int t = threadIdx.x;       // 128 threads
    float inv = 1.f / fmaxf(g_cnt[g], 1.f);
    float p = g_pool[g * 128 + t] * inv;
    float a0 = p * Wlin[2 * t + 0];
    float a1 = p * Wlin[2 * t + 1];
#pragma unroll
    for (int o = 16; o; o >>= 1) {
        a0 += __shfl_xor_sync(0xffffffffu, a0, o);
        a1 += __shfl_xor_sync(0xffffffffu, a1, o);
    }
    __shared__ float sa[4], sb2[4];
    if ((t & 31) == 0) { sa[t >> 5] = a0; sb2[t >> 5] = a1; }
    __syncthreads();
    if (t == 0) out[2 * g + 0] = sa[0] + sa[1] + sa[2] + sa[3] + blin[0];
    if (t == 1) out[2 * g + 1] = sb2[0] + sb2[1] + sb2[2] + sb2[3] + blin[1];
}

// ---------------- launcher ----------------
extern "C" void kernel_launch(void* const* d_in, const int* in_sizes, int n_in,
                              void* d_out, int out_size) {
    const float* x     = (const float*)d_in[0];
    const int*   ei    = (const int*)d_in[1];
    const int*   batch = (const int*)d_in[2];
    const float* Wl1   = (const float*)d_in[3];
    const float* Wr1   = (const float*)d_in[4];
    const float* att1  = (const float*)d_in[5];
    const float* b1    = (const float*)d_in[6];
    const float* gamma = (const float*)d_in[7];
    const float* beta  = (const float*)d_in[8];
    const float* Wl2   = (const float*)d_in[9];
    const float* Wr2   = (const float*)d_in[10];
    const float* att2  = (const float*)d_in[11];
    const float* b2    = (const float*)d_in[12];
    const float* Wlin  = (const float*)d_in[13];
    const float* blin  = (const float*)d_in[14];
    float* out = (float*)d_out;

    void *p_y1, *p_h1, *p_y2, *p_b1h, *p_b1l, *p_b2h, *p_b2l;
    cudaGetSymbolAddress(&p_y1, g_y1);
    cudaGetSymbolAddress(&p_h1, g_h1);
    cudaGetSymbolAddress(&p_y2, g_y2);
    cudaGetSymbolAddress(&p_b1h, g_B1h);
    cudaGetSymbolAddress(&p_b1l, g_B1l);
    cudaGetSymbolAddress(&p_b2h, g_B2h);
    cudaGetSymbolAddress(&p_b2l, g_B2l);
    float* y1 = (float*)p_y1;
    float* h1 = (float*)p_h1;
    float* y2 = (float*)p_y2;

    const int SMEMSZ = 81920 + 2048;  // 2 pipeline buffers + BN scale/shift
    static bool s_init = false;
    static cudaStream_t s1;
    static cudaEvent_t evFork, evJoin;
    if (!s_init) {
        cudaFuncSetAttribute(k_mma<128, false>, cudaFuncAttributeMaxDynamicSharedMemorySize, SMEMSZ);
        cudaFuncSetAttribute(k_mma<256, true>, cudaFuncAttributeMaxDynamicSharedMemorySize, SMEMSZ);
        cudaStreamCreateWithFlags(&s1, cudaStreamNonBlocking);
        cudaEventCreateWithFlags(&evFork, cudaEventDisableTiming);
        cudaEventCreateWithFlags(&evJoin, cudaEventDisableTiming);
        s_init = true;
    }

    const int MB = (NN + 127) / 128;  // 391

    // ---- fork: CSR build on side stream, GEMM path on main stream ----
    cudaEventRecord(evFork, 0);
    cudaStreamWaitEvent(s1, evFork, 0);

    // main stream: weight split -> layer1 GEMM
    k_initMain<<<256, 256>>>();
    k_splitB<<<512, 256>>>(Wl1, Wr1, Wl2, Wr2);
    k_mma<128, false><<<dim3(4, MB), 256, SMEMSZ>>>(
        x, (const __nv_bfloat16*)p_b1h, (const __nv_bfloat16*)p_b1l, y1, 512, NN);

    // side stream: CSR build (independent of GEMM path)
    k_initDeg<<<(NN + 255) / 256, 256, 0, s1>>>();
    k_hist<<<(ET + 255) / 256, 256, 0, s1>>>(ei);
    k_scanA<<<SCB, 1024, 0, s1>>>();
    k_scanB<<<1, 32, 0, s1>>>();
    k_scanC<<<SCB, 1024, 0, s1>>>();
    k_fill<<<(ET + 255) / 256, 256, 0, s1>>>(ei);
    cudaEventRecord(evJoin, s1);
    cudaStreamWaitEvent(0, evJoin, 0);

    // ---- joined: aggregation needs both y1 and CSR ----
    k_agg<2, false><<<(NN * 32 + 255) / 256, 256>>>(y1, att1, b1, h1, nullptr);

    // BatchNorm stats -> affine folded into layer-2 GEMM A-loads
    k_bnstats<<<512, 256>>>(h1);
    k_bnfin<<<1, 256>>>(gamma, beta);

    // Layer 2: y2 = bn(h1) @ [Wl2 | Wr2]
    k_mma<256, true><<<dim3(2, MB), 256, SMEMSZ>>>(
        h1, (const __nv_bfloat16*)p_b2h, (const __nv_bfloat16*)p_b2l, y2, 256, NN);
    k_agg<1, true><<<(NN * 32 + 255) / 256, 256>>>(y2, att2, b2, nullptr, batch);

    // Pool mean + final linear
    k_final<<<GG, 128>>>(Wlin, blin, out);
}

// round 9
// speedup vs baseline: 1.6400x; 1.0531x over previous
#include <cuda_runtime.h>
#include <cuda_bf16.h>
#include <cuda_fp16.h>
#include <math.h>
#include <stdint.h>

#define NN 50000
#define EE 800000
#define ET 850000   // EE + NN self loops
#define GG 512
#define SCB 25      // scan blocks (2048 elems each)

// ---------------- static scratch (no allocations allowed) ----------------
__device__ __align__(128) __half g_y1[(size_t)NN * 512];  // [xl1 | xr1] fp16
__device__ __align__(128) float  g_h1[(size_t)NN * 256];  // post-ELU layer1 output
__device__ __align__(128) __half g_y2[(size_t)NN * 256];  // [xl2 | xr2] fp16
__device__ __align__(128) __nv_bfloat16 g_B1h[512 * 128];  // layer1 B^T hi [n][k]
__device__ __align__(128) __nv_bfloat16 g_B1l[512 * 128];
__device__ __align__(128) __nv_bfloat16 g_B2h[256 * 256];  // layer2 B^T hi [n][k]
__device__ __align__(128) __nv_bfloat16 g_B2l[256 * 256];
__device__ int    g_deg[NN];
__device__ int    g_off[NN + 1];
__device__ int    g_cur[NN];
__device__ int    g_csrc[ET];
__device__ int    g_blksum[32];
__device__ double g_bnsum[256];
__device__ double g_bnsq[256];
__device__ float  g_scale[256];
__device__ float  g_shift[256];
__device__ float  g_pool[GG * 128];
__device__ float  g_cnt[GG];

// ---------------- PTX helpers (baseline sm_80/sm_90 features only) ----------------
__device__ __forceinline__ uint32_t smem_u32(const void* p) {
    uint32_t r;
    asm("{ .reg .u64 t; cvta.to.shared.u64 t, %1; cvt.u32.u64 %0, t; }" : "=r"(r) : "l"(p));
    return r;
}
#define CP_ASYNC16(dst, src) \
    asm volatile("cp.async.cg.shared.global [%0], [%1], 16;" :: "r"(dst), "l"(src) : "memory")
#define CP_COMMIT() asm volatile("cp.async.commit_group;" ::: "memory")
#define CP_WAIT(n)  asm volatile("cp.async.wait_group %0;" :: "n"(n) : "memory")
#define LDM_X4(r0, r1, r2, r3, addr) \
    asm volatile("ldmatrix.sync.aligned.m8n8.x4.shared.b16 {%0,%1,%2,%3}, [%4];" \
        : "=r"(r0), "=r"(r1), "=r"(r2), "=r"(r3) : "r"(addr))
#define MMA_BF16(cc, a, b0v, b1v) \
    asm volatile("mma.sync.aligned.m16n8k16.row.col.f32.bf16.bf16.f32 " \
        "{%0,%1,%2,%3}, {%4,%5,%6,%7}, {%8,%9}, {%0,%1,%2,%3};" \
        : "+f"((cc)[0]), "+f"((cc)[1]), "+f"((cc)[2]), "+f"((cc)[3]) \
        : "r"((a)[0]), "r"((a)[1]), "r"((a)[2]), "r"((a)[3]), "r"(b0v), "r"(b1v))

__device__ __forceinline__ void split_bf16(float v, __nv_bfloat16& h, __nv_bfloat16& l) {
    h = __float2bfloat16(v);
    l = __float2bfloat16(v - __bfloat162float(h));
}
__device__ __forceinline__ uint32_t pk2(float a, float b) {
    __nv_bfloat162 t = __floats2bfloat162_rn(a, b);
    return *reinterpret_cast<uint32_t*>(&t);
}

// ---------------- init ----------------
__global__ void k_initMain() {
    int i = blockIdx.x * blockDim.x + threadIdx.x;  // 65536 threads
    if (i < GG * 128) g_pool[i] = 0.f;
    if (i < GG) g_cnt[i] = 0.f;
    if (i < 256) { g_bnsum[i] = 0.0; g_bnsq[i] = 0.0; }
}

__global__ void k_initDeg() {
    int i = blockIdx.x * blockDim.x + threadIdx.x;
    if (i < NN) g_deg[i] = 0;
}

// ---------------- pre-split & transpose weights (hi/lo bf16) ----------------
__global__ void k_splitB(const float* __restrict__ Wl1, const float* __restrict__ Wr1,
                         const float* __restrict__ Wl2, const float* __restrict__ Wr2) {
    int i = blockIdx.x * blockDim.x + threadIdx.x;  // 131072 threads
    if (i < 512 * 128) {
        int n = i >> 7, k = i & 127;
        float w = (n < 256) ? Wl1[k * 256 + n] : Wr1[k * 256 + (n - 256)];
        split_bf16(w, g_B1h[i], g_B1l[i]);
    } else if (i < 512 * 128 + 256 * 256) {
        int j = i - 512 * 128;
        int n = j >> 8, k = j & 255;
        float w = (n < 128) ? Wl2[k * 128 + n] : Wr2[k * 128 + (n - 128)];
        split_bf16(w, g_B2h[j], g_B2l[j]);
    }
}

// ---------------- CSR build ----------------
__global__ void k_hist(const int* __restrict__ ei) {
    int i = blockIdx.x * blockDim.x + threadIdx.x;
    if (i >= ET) return;
    int dst = (i < EE) ? ei[EE + i] : (i - EE);
    atomicAdd(&g_deg[dst], 1);
}

// hierarchical scan: A) block sums, B) scan block sums, C) full scan + write
__global__ void k_scanA() {  // grid SCB, block 1024
    __shared__ int ws[32];
    const int b = blockIdx.x, t = threadIdx.x;
    const int i = b * 2048 + 2 * t;
    int v0 = 0, v1 = 0;
    if (i + 1 < NN) { int2 p = *(const int2*)&g_deg[i]; v0 = p.x; v1 = p.y; }
    else if (i < NN) v0 = g_deg[i];
    int s = v0 + v1;
#pragma unroll
    for (int o = 16; o; o >>= 1) s += __shfl_xor_sync(0xffffffffu, s, o);
    if ((t & 31) == 0) ws[t >> 5] = s;
    __syncthreads();
    if (t < 32) {
        int x = ws[t];
#pragma unroll
        for (int o = 16; o; o >>= 1) x += __shfl_xor_sync(0xffffffffu, x, o);
        if (t == 0) g_blksum[b] = x;
    }
}

__global__ void k_scanB() {  // 1 block, 32 threads: exclusive scan of SCB sums
    int t = threadIdx.x;
    int v = (t < SCB) ? g_blksum[t] : 0;
    int x = v;
#pragma unroll
    for (int o = 1; o < 32; o <<= 1) {
        int u = __shfl_up_sync(0xffffffffu, x, o);
        if (t >= o) x += u;
    }
    if (t < SCB) g_blksum[t] = x - v;  // exclusive
    if (t == SCB - 1) g_off[NN] = x;   // grand total
}

__global__ void k_scanC() {  // grid SCB, block 1024: full scan + write off/cur
    __shared__ int ws[32];
    const int b = blockIdx.x, t = threadIdx.x;
    const int lane = t & 31, w = t >> 5;
    const int i = b * 2048 + 2 * t;
    int v0 = 0, v1 = 0;
    if (i + 1 < NN) { int2 p = *(const int2*)&g_deg[i]; v0 = p.x; v1 = p.y; }
    else if (i < NN) v0 = g_deg[i];
    int s = v0 + v1;
    int x = s;
#pragma unroll
    for (int o = 1; o < 32; o <<= 1) {
        int u = __shfl_up_sync(0xffffffffu, x, o);
        if (lane >= o) x += u;
    }
    if (lane == 31) ws[w] = x;
    __syncthreads();
    if (w == 0) {
        int y = ws[lane];
#pragma unroll
        for (int o = 1; o < 32; o <<= 1) {
            int u = __shfl_up_sync(0xffffffffu, y, o);
            if (lane >= o) y += u;
        }
        ws[lane] = y;
    }
    __syncthreads();
    int excl = x - s + (w > 0 ? ws[w - 1] : 0) + g_blksum[b];
    if (i < NN) { g_off[i] = excl; g_cur[i] = excl; }
    if (i + 1 < NN) { g_off[i + 1] = excl + v0; g_cur[i + 1] = excl + v0; }
}

__global__ void k_fill(const int* __restrict__ ei) {
    int i = blockIdx.x * blockDim.x + threadIdx.x;
    if (i >= ET) return;
    int src = (i < EE) ? ei[i] : (i - EE);
    int dst = (i < EE) ? ei[EE + i] : (i - EE);
    int p = atomicAdd(&g_cur[dst], 1);
    g_csrc[p] = src;
}

// ---------------- bf16 3-pass mma.sync GEMM with in-register A split ----------------
// C tile (128x128) = (Ah+Al)[M,K] @ (Bh+Bl)^T.  A is fp32 [M,K], split on the fly
// (optionally BN-normalized first). Bh/Bl: pre-split bf16 [Ntot][K].
// Output written as fp16 (half2 stores). 8 warps, 32x64 warp tiles, K chunks of 32.
template <int K, bool NORM>
__global__ void __launch_bounds__(256, 1) k_mma(
    const float* __restrict__ A,
    const __nv_bfloat16* __restrict__ Bh, const __nv_bfloat16* __restrict__ Bl,
    __half* __restrict__ C, int ldc, int M) {
    extern __shared__ __align__(128) char smem[];
    constexpr int NC = K / 32;
    const int tid = threadIdx.x, lane = tid & 31, wid = tid >> 5;
    const int row0 = blockIdx.y * 128, n0 = blockIdx.x * 128;
    const int wm = (wid & 3) * 32, wn = (wid >> 2) * 64;
    const uint32_t sb = smem_u32(smem);
    float* sScale = (float*)(smem + 81920);
    float* sShift = (float*)(smem + 81920 + 1024);

    if (NORM) {
        if (tid < K) { sScale[tid] = g_scale[tid]; sShift[tid] = g_shift[tid]; }
        __syncthreads();
    }

    float c[2][8][4];
#pragma unroll
    for (int mf = 0; mf < 2; mf++)
#pragma unroll
        for (int nf = 0; nf < 8; nf++)
#pragma unroll
            for (int q = 0; q < 4; q++) c[mf][nf][q] = 0.f;

    const int ar = tid >> 1;             // A row within tile
    const int ac = (tid & 1) * 16;       // A col-seg within chunk
    const int agr = min(row0 + ar, M - 1);

    auto ldgA = [&](int ch, float* f) {
        const float* ap = A + (size_t)agr * K + ch * 32 + ac;
#pragma unroll
        for (int q = 0; q < 4; q++) {
            float4 v = *(const float4*)(ap + q * 4);
            f[q * 4 + 0] = v.x; f[q * 4 + 1] = v.y;
            f[q * 4 + 2] = v.z; f[q * 4 + 3] = v.w;
        }
    };
    auto stsA = [&](int ch, float* f) {
        const uint32_t base = sb + (uint32_t)(ch & 1) * 40960u;
        if (NORM) {
            const int c0 = ch * 32 + ac;
#pragma unroll
            for (int i = 0; i < 16; i++) f[i] = fmaf(f[i], sScale[c0 + i], sShift[c0 + i]);
        }
        float h[16], l[16];
#pragma unroll
        for (int i = 0; i < 16; i++) {
            __nv_bfloat16 hb = __float2bfloat16(f[i]);
            h[i] = __bfloat162float(hb);
            l[i] = f[i] - h[i];
        }
        const uint32_t ad = base + (uint32_t)ar * 80u + (uint32_t)ac * 2u;
        uint4 H0 = make_uint4(pk2(h[0], h[1]), pk2(h[2], h[3]), pk2(h[4], h[5]), pk2(h[6], h[7]));
        uint4 H1 = make_uint4(pk2(h[8], h[9]), pk2(h[10], h[11]), pk2(h[12], h[13]), pk2(h[14], h[15]));
        uint4 L0 = make_uint4(pk2(l[0], l[1]), pk2(l[2], l[3]), pk2(l[4], l[5]), pk2(l[6], l[7]));
        uint4 L1 = make_uint4(pk2(l[8], l[9]), pk2(l[10], l[11]), pk2(l[12], l[13]), pk2(l[14], l[15]));
        *(uint4*)(smem + (ad - sb)) = H0;
        *(uint4*)(smem + (ad - sb) + 16) = H1;
        *(uint4*)(smem + (ad - sb) + 10240) = L0;
        *(uint4*)(smem + (ad - sb) + 10240 + 16) = L1;
    };
    auto issueB = [&](int ch) {
        const int k0 = ch * 32;
        const uint32_t base = sb + (uint32_t)(ch & 1) * 40960u + 20480u;
#pragma unroll
        for (int j = 0; j < 2; j++) {
            int seg = tid + 256 * j;
            int r = seg >> 2, s = seg & 3;
            const void* srch = Bh + (size_t)(n0 + r) * K + k0 + s * 8;
            const void* srcl = Bl + (size_t)(n0 + r) * K + k0 + s * 8;
            uint32_t dst = base + (uint32_t)r * 80u + (uint32_t)s * 16u;
            CP_ASYNC16(dst, srch);
            CP_ASYNC16(dst + 10240u, srcl);
        }
    };

    // prologue
    float areg[16];
    ldgA(0, areg);
    stsA(0, areg);
    issueB(0);
    CP_COMMIT();
    if (NC > 1) {
        issueB(1);
        CP_COMMIT();
        ldgA(1, areg);
    }

    // ldmatrix per-lane address pieces
    const int grp = lane >> 3, r8 = lane & 7;
    const uint32_t a_row = (uint32_t)(((grp & 1) ? 8 : 0) + r8);
    const uint32_t a_k16 = (grp & 2) ? 16u : 0u;
    const uint32_t b_row = (uint32_t)(((grp & 2) ? 8 : 0) + r8);
    const uint32_t b_k16 = (grp & 1) ? 16u : 0u;

    for (int ch = 0; ch < NC; ch++) {
        if (ch + 1 < NC) { CP_WAIT(1); } else { CP_WAIT(0); }
        __syncthreads();
        const uint32_t sA = sb + (uint32_t)(ch & 1) * 40960u;
#pragma unroll
        for (int ks = 0; ks < 2; ks++) {
            const uint32_t ko = (uint32_t)ks * 32u;
            uint32_t ah[2][4], al[2][4], bh[4][4], bl[4][4];
#pragma unroll
            for (int mf = 0; mf < 2; mf++) {
                uint32_t addr = sA + ((uint32_t)(wm + mf * 16) + a_row) * 80u + ko + a_k16;
                LDM_X4(ah[mf][0], ah[mf][1], ah[mf][2], ah[mf][3], addr);
                LDM_X4(al[mf][0], al[mf][1], al[mf][2], al[mf][3], addr + 10240u);
            }
#pragma unroll
            for (int pf = 0; pf < 4; pf++) {
                uint32_t addr = sA + 20480u + ((uint32_t)(wn + pf * 16) + b_row) * 80u + ko + b_k16;
                LDM_X4(bh[pf][0], bh[pf][1], bh[pf][2], bh[pf][3], addr);
                LDM_X4(bl[pf][0], bl[pf][1], bl[pf][2], bl[pf][3], addr + 10240u);
            }
#pragma unroll
            for (int mf = 0; mf < 2; mf++)
#pragma unroll
                for (int nf = 0; nf < 8; nf++) {
                    const int pf = nf >> 1, h = (nf & 1) * 2;
                    MMA_BF16(c[mf][nf], ah[mf], bh[pf][h], bh[pf][h + 1]);
                    MMA_BF16(c[mf][nf], ah[mf], bl[pf][h], bl[pf][h + 1]);
                    MMA_BF16(c[mf][nf], al[mf], bh[pf][h], bh[pf][h + 1]);
                }
        }
        if (ch + 1 < NC) {
            stsA(ch + 1, areg);               // other buffer: safe pre-sync
            if (ch + 2 < NC) ldgA(ch + 2, areg);
        }
        __syncthreads();
        if (ch + 2 < NC) {
            issueB(ch + 2);                    // reuses buffer (ch&1): safe post-sync
            CP_COMMIT();
        }
    }

    // epilogue (fp16 stores)
    const int g = lane >> 2, tg = lane & 3;
#pragma unroll
    for (int mf = 0; mf < 2; mf++) {
        int row = row0 + wm + mf * 16 + g;
#pragma unroll
        for (int nf = 0; nf < 8; nf++) {
            int col = n0 + wn + nf * 8 + 2 * tg;
            if (row < M)
                *(__half2*)(C + (size_t)row * ldc + col) = __floats2half2_rn(c[mf][nf][0], c[mf][nf][1]);
            if (row + 8 < M)
                *(__half2*)(C + (size_t)(row + 8) * ldc + col) = __floats2half2_rn(c[mf][nf][2], c[mf][nf][3]);
        }
    }
}

// ---------------- GATv2 aggregation: warp per dst node, online softmax ----------------
// y stored fp16; each lane handles channel pairs c = 2*lane + 64*r.
template <int HEADS, bool FINAL>
__global__ void k_agg(const __half* __restrict__ y,     // [NN, 2*CH]  = [xl | xr] fp16
                      const float* __restrict__ att,    // [CH]
                      const float* __restrict__ bias,   // [CH]
                      float* __restrict__ hout,         // [NN, CH]  (if !FINAL)
                      const int* __restrict__ batch) {
    constexpr int CH = HEADS * 128;
    constexpr int R2 = CH / 64;        // half2 regs per lane
    constexpr int HR2 = R2 / HEADS;    // regs per head (=2)
    const int lane = threadIdx.x & 31;
    const int t = (blockIdx.x * blockDim.x + threadIdx.x) >> 5;
    if (t >= NN) return;

    const __half* yt = y + (size_t)t * (2 * CH) + CH;  // xr[t]
    float2 xr[R2], attv[R2], acc[R2];
#pragma unroll
    for (int r = 0; r < R2; r++) {
        int c = 2 * lane + 64 * r;
        xr[r] = __half22float2(*(const __half2*)(yt + c));
        attv[r] = make_float2(att[c], att[c + 1]);
        acc[r] = make_float2(0.f, 0.f);
    }
    float emax[HEADS], den[HEADS];
#pragma unroll
    for (int h = 0; h < HEADS; h++) { emax[h] = -1e30f; den[h] = 0.f; }

    const int s0 = g_off[t], s1 = g_off[t + 1];
#pragma unroll 2
    for (int j = s0; j < s1; j++) {
        int s = g_csrc[j];
        const __half* ys = y + (size_t)s * (2 * CH);  // xl[s]
        float2 xv[R2];
        float d[HEADS];
#pragma unroll
        for (int h = 0; h < HEADS; h++) d[h] = 0.f;
#pragma unroll
        for (int r = 0; r < R2; r++) {
            float2 v = __half22float2(*(const __half2*)(ys + 2 * lane + 64 * r));
            xv[r] = v;
            float mx = v.x + xr[r].x;
            float my = v.y + xr[r].y;
            mx = (mx > 0.f) ? mx : 0.2f * mx;  // leaky relu
            my = (my > 0.f) ? my : 0.2f * my;
            const int h = r / HR2;
            d[h] = fmaf(mx, attv[r].x, d[h]);
            d[h] = fmaf(my, attv[r].y, d[h]);
        }
#pragma unroll
        for (int h = 0; h < HEADS; h++) {
#pragma unroll
            for (int o = 16; o; o >>= 1) d[h] += __shfl_xor_sync(0xffffffffu, d[h], o);
        }
        float ex[HEADS];
#pragma unroll
        for (int h = 0; h < HEADS; h++) {
            if (d[h] > emax[h]) {
                float corr = __expf(emax[h] - d[h]);
                den[h] *= corr;
#pragma unroll
                for (int r = h * HR2; r < (h + 1) * HR2; r++) {
                    acc[r].x *= corr;
                    acc[r].y *= corr;
                }
                emax[h] = d[h];
                ex[h] = 1.f;
            } else {
                ex[h] = __expf(d[h] - emax[h]);
            }
            den[h] += ex[h];
        }
#pragma unroll
        for (int r = 0; r < R2; r++) {
            const float e = ex[r / HR2];
            acc[r].x = fmaf(e, xv[r].x, acc[r].x);
            acc[r].y = fmaf(e, xv[r].y, acc[r].y);
        }
    }

    if (FINAL) {
        int g = batch[t];
#pragma unroll
        for (int r = 0; r < R2; r++) {
            int c = 2 * lane + 64 * r;
            float inv = 1.f / (den[r / HR2] + 1e-16f);
            atomicAdd(&g_pool[g * CH + c], acc[r].x * inv + bias[c]);
            atomicAdd(&g_pool[g * CH + c + 1], acc[r].y * inv + bias[c + 1]);
        }
        if (lane == 0) atomicAdd(&g_cnt[g], 1.f);
    } else {
#pragma unroll
        for (int r = 0; r < R2; r++) {
            int c = 2 * lane + 64 * r;
            float inv = 1.f / (den[r / HR2] + 1e-16f);
            float vx = acc[r].x * inv + bias[c];
            float vy = acc[r].y * inv + bias[c + 1];
            vx = (vx > 0.f) ? vx : expm1f(vx);  // ELU
            vy = (vy > 0.f) ? vy : expm1f(vy);
            *(float2*)(hout + (size_t)t * CH + c) = make_float2(vx, vy);
        }
    }
}

// ---------------- BatchNorm stats + finalize ----------------
__global__ void k_bnstats(const float* __restrict__ h) {
    int c = threadIdx.x;  // 256
    float s = 0.f, q = 0.f;
    for (int r = blockIdx.x; r < NN; r += gridDim.x) {
        float v = h[(size_t)r * 256 + c];
        s += v;
        q = fmaf(v, v, q);
    }
    atomicAdd(&g_bnsum[c], (double)s);
    atomicAdd(&g_bnsq[c], (double)q);
}

__global__ void k_bnfin(const float* __restrict__ gamma, const float* __restrict__ beta) {
    int c = threadIdx.x;  // 256
    float mu = (float)(g_bnsum[c] / (double)NN);
    float var = (float)(g_bnsq[c] / (double)NN) - mu * mu;
    float sc = gamma[c] * rsqrtf(var + 1e-5f);
    g_scale[c] = sc;
    g_shift[c] = beta[c] - mu * sc;
}

// ---------------- final: pooled mean @ Wlin + blin ----------------
__global__ void k_final(const float* __restrict__ Wlin, const float* __restrict__ blin,
                        float* __restrict__ out) {
    int g = blockIdx.x;        // GG blocks
    int t = threadIdx.x;       // 128 threads
    float inv = 1.f / fmaxf(g_cnt[g], 1.f);
    float p = g_pool[g * 128 + t] * inv;
    float a0 = p * Wlin[2 * t + 0];
    float a1 = p * Wlin[2 * t + 1];
#pragma unroll
    for (int o = 16; o; o >>= 1) {
        a0 += __shfl_xor_sync(0xffffffffu, a0, o);
        a1 += __shfl_xor_sync(0xffffffffu, a1, o);
    }
    __shared__ float sa[4], sb2[4];
    if ((t & 31) == 0) { sa[t >> 5] = a0; sb2[t >> 5] = a1; }
    __syncthreads();
    if (t == 0) out[2 * g + 0] = sa[0] + sa[1] + sa[2] + sa[3] + blin[0];
    if (t == 1) out[2 * g + 1] = sb2[0] + sb2[1] + sb2[2] + sb2[3] + blin[1];
}

// ---------------- launcher ----------------
extern "C" void kernel_launch(void* const* d_in, const int* in_sizes, int n_in,
                              void* d_out, int out_size) {
    const float* x     = (const float*)d_in[0];
    const int*   ei    = (const int*)d_in[1];
    const int*   batch = (const int*)d_in[2];
    const float* Wl1   = (const float*)d_in[3];
    const float* Wr1   = (const float*)d_in[4];
    const float* att1  = (const float*)d_in[5];
    const float* b1    = (const float*)d_in[6];
    const float* gamma = (const float*)d_in[7];
    const float* beta  = (const float*)d_in[8];
    const float* Wl2   = (const float*)d_in[9];
    const float* Wr2   = (const float*)d_in[10];
    const float* att2  = (const float*)d_in[11];
    const float* b2    = (const float*)d_in[12];
    const float* Wlin  = (const float*)d_in[13];
    const float* blin  = (const float*)d_in[14];
    float* out = (float*)d_out;

    void *p_y1, *p_h1, *p_y2, *p_b1h, *p_b1l, *p_b2h, *p_b2l;
    cudaGetSymbolAddress(&p_y1, g_y1);
    cudaGetSymbolAddress(&p_h1, g_h1);
    cudaGetSymbolAddress(&p_y2, g_y2);
    cudaGetSymbolAddress(&p_b1h, g_B1h);
    cudaGetSymbolAddress(&p_b1l, g_B1l);
    cudaGetSymbolAddress(&p_b2h, g_B2h);
    cudaGetSymbolAddress(&p_b2l, g_B2l);
    __half* y1 = (__half*)p_y1;
    float*  h1 = (float*)p_h1;
    __half* y2 = (__half*)p_y2;

    const int SMEMSZ = 81920 + 2048;  // 2 pipeline buffers + BN scale/shift
    static bool s_init = false;
    static cudaStream_t s1;
    static cudaEvent_t evFork, evJoin;
    if (!s_init) {
        cudaFuncSetAttribute(k_mma<128, false>, cudaFuncAttributeMaxDynamicSharedMemorySize, SMEMSZ);
        cudaFuncSetAttribute(k_mma<256, true>, cudaFuncAttributeMaxDynamicSharedMemorySize, SMEMSZ);
        cudaStreamCreateWithFlags(&s1, cudaStreamNonBlocking);
        cudaEventCreateWithFlags(&evFork, cudaEventDisableTiming);
        cudaEventCreateWithFlags(&evJoin, cudaEventDisableTiming);
        s_init = true;
    }

    const int MB = (NN + 127) / 128;  // 391

    // ---- fork: CSR build on side stream, GEMM path on main stream ----
    cudaEventRecord(evFork, 0);
    cudaStreamWaitEvent(s1, evFork, 0);

    // main stream: weight split -> layer1 GEMM
    k_initMain<<<256, 256>>>();
    k_splitB<<<512, 256>>>(Wl1, Wr1, Wl2, Wr2);
    k_mma<128, false><<<dim3(4, MB), 256, SMEMSZ>>>(
        x, (const __nv_bfloat16*)p_b1h, (const __nv_bfloat16*)p_b1l, y1, 512, NN);

    // side stream: CSR build (independent of GEMM path)
    k_initDeg<<<(NN + 255) / 256, 256, 0, s1>>>();
    k_hist<<<(ET + 255) / 256, 256, 0, s1>>>(ei);
    k_scanA<<<SCB, 1024, 0, s1>>>();
    k_scanB<<<1, 32, 0, s1>>>();
    k_scanC<<<SCB, 1024, 0, s1>>>();
    k_fill<<<(ET + 255) / 256, 256, 0, s1>>>(ei);
    cudaEventRecord(evJoin, s1);
    cudaStreamWaitEvent(0, evJoin, 0);

    // ---- joined: aggregation needs both y1 and CSR ----
    k_agg<2, false><<<(NN * 32 + 255) / 256, 256>>>(y1, att1, b1, h1, nullptr);

    // BatchNorm stats -> affine folded into layer-2 GEMM A-loads
    k_bnstats<<<512, 256>>>(h1);
    k_bnfin<<<1, 256>>>(gamma, beta);

    // Layer 2: y2 = bn(h1) @ [Wl2 | Wr2]
    k_mma<256, true><<<dim3(2, MB), 256, SMEMSZ>>>(
        h1, (const __nv_bfloat16*)p_b2h, (const __nv_bfloat16*)p_b2l, y2, 256, NN);
    k_agg<1, true><<<(NN * 32 + 255) / 256, 256>>>(y2, att2, b2, nullptr, batch);

    // Pool mean + final linear
    k_final<<<GG, 128>>>(Wlin, blin, out);
}

// round 11
// speedup vs baseline: 1.9767x; 1.2053x over previous
#include <cuda_runtime.h>
#include <cuda_fp16.h>
#include <math.h>
#include <stdint.h>

#define NN 50000
#define EE 800000
#define ET 850000   // EE + NN self loops
#define GG 512
#define SCB 25      // scan blocks (2048 elems each)

// ---------------- static scratch (no allocations allowed) ----------------
__device__ __align__(128) __half g_y1[(size_t)NN * 512];  // [xl1 | xr1] fp16
__device__ __align__(128) __half g_h1[(size_t)NN * 256];  // post-ELU layer1 output fp16
__device__ __align__(128) __half g_y2[(size_t)NN * 256];  // [xl2 | xr2] fp16
__device__ __align__(128) __half g_B1[512 * 128];  // layer1 B^T fp16 [n][k]
__device__ __align__(128) __half g_B2[256 * 256];  // layer2 B^T fp16 [n][k]
__device__ int    g_deg[NN];
__device__ int    g_off[NN + 1];
__device__ int    g_cur[NN];
__device__ int    g_csrc[ET];
__device__ int    g_blksum[32];
__device__ double g_bnsum[256];
__device__ double g_bnsq[256];
__device__ float  g_scale[256];
__device__ float  g_shift[256];
__device__ float  g_pool[GG * 128];
__device__ float  g_cnt[GG];

// ---------------- PTX helpers (baseline sm_80/sm_90 features only) ----------------
__device__ __forceinline__ uint32_t smem_u32(const void* p) {
    uint32_t r;
    asm("{ .reg .u64 t; cvta.to.shared.u64 t, %1; cvt.u32.u64 %0, t; }" : "=r"(r) : "l"(p));
    return r;
}
#define CP_ASYNC16(dst, src) \
    asm volatile("cp.async.cg.shared.global [%0], [%1], 16;" :: "r"(dst), "l"(src) : "memory")
#define CP_COMMIT() asm volatile("cp.async.commit_group;" ::: "memory")
#define CP_WAIT(n)  asm volatile("cp.async.wait_group %0;" :: "n"(n) : "memory")
#define LDM_X4(r0, r1, r2, r3, addr) \
    asm volatile("ldmatrix.sync.aligned.m8n8.x4.shared.b16 {%0,%1,%2,%3}, [%4];" \
        : "=r"(r0), "=r"(r1), "=r"(r2), "=r"(r3) : "r"(addr))
#define MMA_F16(cc, a, b0v, b1v) \
    asm volatile("mma.sync.aligned.m16n8k16.row.col.f32.f16.f16.f32 " \
        "{%0,%1,%2,%3}, {%4,%5,%6,%7}, {%8,%9}, {%0,%1,%2,%3};" \
        : "+f"((cc)[0]), "+f"((cc)[1]), "+f"((cc)[2]), "+f"((cc)[3]) \
        : "r"((a)[0]), "r"((a)[1]), "r"((a)[2]), "r"((a)[3]), "r"(b0v), "r"(b1v))

__device__ __forceinline__ uint32_t pkh2(float a, float b) {
    __half2 t = __floats2half2_rn(a, b);
    return *reinterpret_cast<uint32_t*>(&t);
}

// ---------------- init ----------------
__global__ void k_initMain() {
    int i = blockIdx.x * blockDim.x + threadIdx.x;  // 65536 threads
    if (i < GG * 128) g_pool[i] = 0.f;
    if (i < GG) g_cnt[i] = 0.f;
    if (i < 256) { g_bnsum[i] = 0.0; g_bnsq[i] = 0.0; }
}

__global__ void k_initDeg() {
    int i = blockIdx.x * blockDim.x + threadIdx.x;
    if (i < NN) g_deg[i] = 0;
}

// ---------------- convert & transpose weights (fp16) ----------------
__global__ void k_cvtB(const float* __restrict__ Wl1, const float* __restrict__ Wr1,
                       const float* __restrict__ Wl2, const float* __restrict__ Wr2) {
    int i = blockIdx.x * blockDim.x + threadIdx.x;  // 131072 threads
    if (i < 512 * 128) {
        int n = i >> 7, k = i & 127;
        float w = (n < 256) ? Wl1[k * 256 + n] : Wr1[k * 256 + (n - 256)];
        g_B1[i] = __float2half(w);
    } else if (i < 512 * 128 + 256 * 256) {
        int j = i - 512 * 128;
        int n = j >> 8, k = j & 255;
        float w = (n < 128) ? Wl2[k * 128 + n] : Wr2[k * 128 + (n - 128)];
        g_B2[j] = __float2half(w);
    }
}

// ---------------- CSR build ----------------
__global__ void k_hist(const int* __restrict__ ei) {
    int i = blockIdx.x * blockDim.x + threadIdx.x;
    if (i >= ET) return;
    int dst = (i < EE) ? ei[EE + i] : (i - EE);
    atomicAdd(&g_deg[dst], 1);
}

// hierarchical scan: A) block sums, B) scan block sums, C) full scan + write
__global__ void k_scanA() {  // grid SCB, block 1024
    __shared__ int ws[32];
    const int b = blockIdx.x, t = threadIdx.x;
    const int i = b * 2048 + 2 * t;
    int v0 = 0, v1 = 0;
    if (i + 1 < NN) { int2 p = *(const int2*)&g_deg[i]; v0 = p.x; v1 = p.y; }
    else if (i < NN) v0 = g_deg[i];
    int s = v0 + v1;
#pragma unroll
    for (int o = 16; o; o >>= 1) s += __shfl_xor_sync(0xffffffffu, s, o);
    if ((t & 31) == 0) ws[t >> 5] = s;
    __syncthreads();
    if (t < 32) {
        int x = ws[t];
#pragma unroll
        for (int o = 16; o; o >>= 1) x += __shfl_xor_sync(0xffffffffu, x, o);
        if (t == 0) g_blksum[b] = x;
    }
}

__global__ void k_scanB() {  // 1 block, 32 threads: exclusive scan of SCB sums
    int t = threadIdx.x;
    int v = (t < SCB) ? g_blksum[t] : 0;
    int x = v;
#pragma unroll
    for (int o = 1; o < 32; o <<= 1) {
        int u = __shfl_up_sync(0xffffffffu, x, o);
        if (t >= o) x += u;
    }
    if (t < SCB) g_blksum[t] = x - v;  // exclusive
    if (t == SCB - 1) g_off[NN] = x;   // grand total
}

__global__ void k_scanC() {  // grid SCB, block 1024: full scan + write off/cur
    __shared__ int ws[32];
    const int b = blockIdx.x, t = threadIdx.x;
    const int lane = t & 31, w = t >> 5;
    const int i = b * 2048 + 2 * t;
    int v0 = 0, v1 = 0;
    if (i + 1 < NN) { int2 p = *(const int2*)&g_deg[i]; v0 = p.x; v1 = p.y; }
    else if (i < NN) v0 = g_deg[i];
    int s = v0 + v1;
    int x = s;
#pragma unroll
    for (int o = 1; o < 32; o <<= 1) {
        int u = __shfl_up_sync(0xffffffffu, x, o);
        if (lane >= o) x += u;
    }
    if (lane == 31) ws[w] = x;
    __syncthreads();
    if (w == 0) {
        int y = ws[lane];
#pragma unroll
        for (int o = 1; o < 32; o <<= 1) {
            int u = __shfl_up_sync(0xffffffffu, y, o);
            if (lane >= o) y += u;
        }
        ws[lane] = y;
    }
    __syncthreads();
    int excl = x - s + (w > 0 ? ws[w - 1] : 0) + g_blksum[b];
    if (i < NN) { g_off[i] = excl; g_cur[i] = excl; }
    if (i + 1 < NN) { g_off[i + 1] = excl + v0; g_cur[i + 1] = excl + v0; }
}

__global__ void k_fill(const int* __restrict__ ei) {
    int i = blockIdx.x * blockDim.x + threadIdx.x;
    if (i >= ET) return;
    int src = (i < EE) ? ei[i] : (i - EE);
    int dst = (i < EE) ? ei[EE + i] : (i - EE);
    int p = atomicAdd(&g_cur[dst], 1);
    g_csrc[p] = src;
}

// ---------------- single-pass fp16 mma.sync GEMM ----------------
// C tile (128x128) = A[M,K] @ B^T, fp16 inputs, fp32 accum, fp16 output.
// A: fp32 (layer1, TA=float) or fp16 (layer2, TA=__half; BN affine applied on load).
// B: pre-converted fp16 [Ntot][K]. 8 warps, 32x64 warp tiles, K chunks of 32,
// double-buffered (A reg prefetch, B cp.async). Stage: A(10240B) | B(10240B), stride 80B.
template <int K, bool NORM, typename TA>
__global__ void __launch_bounds__(256, 2) k_mma(
    const TA* __restrict__ A,
    const __half* __restrict__ B,
    __half* __restrict__ C, int ldc, int M) {
    extern __shared__ __align__(128) char smem[];
    constexpr int NC = K / 32;
    const int tid = threadIdx.x, lane = tid & 31, wid = tid >> 5;
    const int row0 = blockIdx.y * 128, n0 = blockIdx.x * 128;
    const int wm = (wid & 3) * 32, wn = (wid >> 2) * 64;
    const uint32_t sb = smem_u32(smem);
    float* sScale = (float*)(smem + 40960);
    float* sShift = (float*)(smem + 40960 + 1024);

    if (NORM) {
        if (tid < K) { sScale[tid] = g_scale[tid]; sShift[tid] = g_shift[tid]; }
        __syncthreads();
    }

    float c[2][8][4];
#pragma unroll
    for (int mf = 0; mf < 2; mf++)
#pragma unroll
        for (int nf = 0; nf < 8; nf++)
#pragma unroll
            for (int q = 0; q < 4; q++) c[mf][nf][q] = 0.f;

    const int ar = tid >> 1;             // A row within tile
    const int ac = (tid & 1) * 16;       // A col-seg within chunk
    const int agr = min(row0 + ar, M - 1);

    auto ldgA = [&](int ch, float* f) {
        const TA* ap = A + (size_t)agr * K + ch * 32 + ac;
        if (sizeof(TA) == 4) {
            const float* fp = (const float*)ap;
#pragma unroll
            for (int q = 0; q < 4; q++) {
                float4 v = *(const float4*)(fp + q * 4);
                f[q * 4 + 0] = v.x; f[q * 4 + 1] = v.y;
                f[q * 4 + 2] = v.z; f[q * 4 + 3] = v.w;
            }
        } else {
            const __half2* hp = (const __half2*)ap;
#pragma unroll
            for (int q = 0; q < 8; q++) {
                float2 v = __half22float2(hp[q]);
                f[q * 2 + 0] = v.x; f[q * 2 + 1] = v.y;
            }
        }
    };
    auto stsA = [&](int ch, float* f) {
        const uint32_t base = (uint32_t)(ch & 1) * 20480u;
        if (NORM) {
            const int c0 = ch * 32 + ac;
#pragma unroll
            for (int i = 0; i < 16; i++) f[i] = fmaf(f[i], sScale[c0 + i], sShift[c0 + i]);
        }
        uint4 H0 = make_uint4(pkh2(f[0], f[1]), pkh2(f[2], f[3]), pkh2(f[4], f[5]), pkh2(f[6], f[7]));
        uint4 H1 = make_uint4(pkh2(f[8], f[9]), pkh2(f[10], f[11]), pkh2(f[12], f[13]), pkh2(f[14], f[15]));
        const uint32_t off = base + (uint32_t)ar * 80u + (uint32_t)ac * 2u;
        *(uint4*)(smem + off) = H0;
        *(uint4*)(smem + off + 16) = H1;
    };
    auto issueB = [&](int ch) {
        const int k0 = ch * 32;
        const uint32_t base = sb + (uint32_t)(ch & 1) * 20480u + 10240u;
#pragma unroll
        for (int j = 0; j < 2; j++) {
            int seg = tid + 256 * j;
            int r = seg >> 2, s = seg & 3;
            const void* src = B + (size_t)(n0 + r) * K + k0 + s * 8;
            uint32_t dst = base + (uint32_t)r * 80u + (uint32_t)s * 16u;
            CP_ASYNC16(dst, src);
        }
    };

    // prologue
    float areg[16];
    ldgA(0, areg);
    stsA(0, areg);
    issueB(0);
    CP_COMMIT();
    if (NC > 1) {
        issueB(1);
        CP_COMMIT();
        ldgA(1, areg);
    }

    // ldmatrix per-lane address pieces
    const int grp = lane >> 3, r8 = lane & 7;
    const uint32_t a_row = (uint32_t)(((grp & 1) ? 8 : 0) + r8);
    const uint32_t a_k16 = (grp & 2) ? 16u : 0u;
    const uint32_t b_row = (uint32_t)(((grp & 2) ? 8 : 0) + r8);
    const uint32_t b_k16 = (grp & 1) ? 16u : 0u;

    for (int ch = 0; ch < NC; ch++) {
        if (ch + 1 < NC) { CP_WAIT(1); } else { CP_WAIT(0); }
        __syncthreads();
        const uint32_t sA = sb + (uint32_t)(ch & 1) * 20480u;
#pragma unroll
        for (int ks = 0; ks < 2; ks++) {
            const uint32_t ko = (uint32_t)ks * 32u;
            uint32_t ah[2][4], bh[4][4];
#pragma unroll
            for (int mf = 0; mf < 2; mf++) {
                uint32_t addr = sA + ((uint32_t)(wm + mf * 16) + a_row) * 80u + ko + a_k16;
                LDM_X4(ah[mf][0], ah[mf][1], ah[mf][2], ah[mf][3], addr);
            }
#pragma unroll
            for (int pf = 0; pf < 4; pf++) {
                uint32_t addr = sA + 10240u + ((uint32_t)(wn + pf * 16) + b_row) * 80u + ko + b_k16;
                LDM_X4(bh[pf][0], bh[pf][1], bh[pf][2], bh[pf][3], addr);
            }
#pragma unroll
            for (int mf = 0; mf < 2; mf++)
#pragma unroll
                for (int nf = 0; nf < 8; nf++) {
                    const int pf = nf >> 1, h = (nf & 1) * 2;
                    MMA_F16(c[mf][nf], ah[mf], bh[pf][h], bh[pf][h + 1]);
                }
        }
        if (ch + 1 < NC) {
            stsA(ch + 1, areg);               // other buffer: safe pre-sync
            if (ch + 2 < NC) ldgA(ch + 2, areg);
        }
        __syncthreads();
        if (ch + 2 < NC) {
            issueB(ch + 2);                    // reuses buffer (ch&1): safe post-sync
            CP_COMMIT();
        }
    }

    // epilogue (fp16 stores)
    const int g = lane >> 2, tg = lane & 3;
#pragma unroll
    for (int mf = 0; mf < 2; mf++) {
        int row = row0 + wm + mf * 16 + g;
#pragma unroll
        for (int nf = 0; nf < 8; nf++) {
            int col = n0 + wn + nf * 8 + 2 * tg;
            if (row < M)
                *(__half2*)(C + (size_t)row * ldc + col) = __floats2half2_rn(c[mf][nf][0], c[mf][nf][1]);
            if (row + 8 < M)
                *(__half2*)(C + (size_t)(row + 8) * ldc + col) = __floats2half2_rn(c[mf][nf][2], c[mf][nf][3]);
        }
    }
}

// ---------------- GATv2 aggregation: warp per dst node, online softmax ----------------
// y stored fp16; each lane handles channel pairs c = 2*lane + 64*r.
template <int HEADS, bool FINAL>
__global__ void k_agg(const __half* __restrict__ y,     // [NN, 2*CH]  = [xl | xr] fp16
                      const float* __restrict__ att,    // [CH]
                      const float* __restrict__ bias,   // [CH]
                      __half* __restrict__ hout,        // [NN, CH] fp16 (if !FINAL)
                      const int* __restrict__ batch) {
    constexpr int CH = HEADS * 128;
    constexpr int R2 = CH / 64;        // half2 regs per lane
    constexpr int HR2 = R2 / HEADS;    // regs per head (=2)
    const int lane = threadIdx.x & 31;
    const int t = (blockIdx.x * blockDim.x + threadIdx.x) >> 5;
    if (t >= NN) return;

    const __half* yt = y + (size_t)t * (2 * CH) + CH;  // xr[t]
    float2 xr[R2], attv[R2], acc[R2];
#pragma unroll
    for (int r = 0; r < R2; r++) {
        int c = 2 * lane + 64 * r;
        xr[r] = __half22float2(*(const __half2*)(yt + c));
        attv[r] = make_float2(att[c], att[c + 1]);
        acc[r] = make_float2(0.f, 0.f);
    }
    float emax[HEADS], den[HEADS];
#pragma unroll
    for (int h = 0; h < HEADS; h++) { emax[h] = -1e30f; den[h] = 0.f; }

    const int s0 = g_off[t], s1 = g_off[t + 1];
#pragma unroll 2
    for (int j = s0; j < s1; j++) {
        int s = g_csrc[j];
        const __half* ys = y + (size_t)s * (2 * CH);  // xl[s]
        float2 xv[R2];
        float d[HEADS];
#pragma unroll
        for (int h = 0; h < HEADS; h++) d[h] = 0.f;
#pragma unroll
        for (int r = 0; r < R2; r++) {
            float2 v = __half22float2(*(const __half2*)(ys + 2 * lane + 64 * r));
            xv[r] = v;
            float mx = v.x + xr[r].x;
            float my = v.y + xr[r].y;
            mx = (mx > 0.f) ? mx : 0.2f * mx;  // leaky relu
            my = (my > 0.f) ? my : 0.2f * my;
            const int h = r / HR2;
            d[h] = fmaf(mx, attv[r].x, d[h]);
            d[h] = fmaf(my, attv[r].y, d[h]);
        }
#pragma unroll
        for (int h = 0; h < HEADS; h++) {
#pragma unroll
            for (int o = 16; o; o >>= 1) d[h] += __shfl_xor_sync(0xffffffffu, d[h], o);
        }
        float ex[HEADS];
#pragma unroll
        for (int h = 0; h < HEADS; h++) {
            if (d[h] > emax[h]) {
                float corr = __expf(emax[h] - d[h]);
                den[h] *= corr;
#pragma unroll
                for (int r = h * HR2; r < (h + 1) * HR2; r++) {
                    acc[r].x *= corr;
                    acc[r].y *= corr;
                }
                emax[h] = d[h];
                ex[h] = 1.f;
            } else {
                ex[h] = __expf(d[h] - emax[h]);
            }
            den[h] += ex[h];
        }
#pragma unroll
        for (int r = 0; r < R2; r++) {
            const float e = ex[r / HR2];
            acc[r].x = fmaf(e, xv[r].x, acc[r].x);
            acc[r].y = fmaf(e, xv[r].y, acc[r].y);
        }
    }

    if (FINAL) {
        int g = batch[t];
#pragma unroll
        for (int r = 0; r < R2; r++) {
            int c = 2 * lane + 64 * r;
            float inv = 1.f / (den[r / HR2] + 1e-16f);
            atomicAdd(&g_pool[g * 128 + c], acc[r].x * inv + bias[c]);
            atomicAdd(&g_pool[g * 128 + c + 1], acc[r].y * inv + bias[c + 1]);
        }
        if (lane == 0) atomicAdd(&g_cnt[g], 1.f);
    } else {
#pragma unroll
        for (int r = 0; r < R2; r++) {
            int c = 2 * lane + 64 * r;
            float inv = 1.f / (den[r / HR2] + 1e-16f);
            float vx = acc[r].x * inv + bias[c];
            float vy = acc[r].y * inv + bias[c + 1];
            vx = (vx > 0.f) ? vx : expm1f(vx);  // ELU
            vy = (vy > 0.f) ? vy : expm1f(vy);
            *(__half2*)(hout + (size_t)t * CH + c) = __floats2half2_rn(vx, vy);
        }
    }
}

// ---------------- BatchNorm stats + finalize ----------------
__global__ void k_bnstats(const __half* __restrict__ h) {
    int c = threadIdx.x;  // 256
    float s = 0.f, q = 0.f;
    for (int r = blockIdx.x; r < NN; r += gridDim.x) {
        float v = __half2float(h[(size_t)r * 256 + c]);
        s += v;
        q = fmaf(v, v, q);
    }
    atomicAdd(&g_bnsum[c], (double)s);
    atomicAdd(&g_bnsq[c], (double)q);
}

__global__ void k_bnfin(const float* __restrict__ gamma, const float* __restrict__ beta) {
    int c = threadIdx.x;  // 256
    float mu = (float)(g_bnsum[c] / (double)NN);
    float var = (float)(g_bnsq[c] / (double)NN) - mu * mu;
    float sc = gamma[c] * rsqrtf(var + 1e-5f);
    g_scale[c] = sc;
    g_shift[c] = beta[c] - mu * sc;
}

// ---------------- final: pooled mean @ Wlin + blin ----------------
__global__ void k_final(const float* __restrict__ Wlin, const float* __restrict__ blin,
                        float* __restrict__ out) {
    int g = blockIdx.x;        // GG blocks
    int t = threadIdx.x;       // 128 threads
    float inv = 1.f / fmaxf(g_cnt[g], 1.f);
    float p = g_pool[g * 128 + t] * inv;
    float a0 = p * Wlin[2 * t + 0];
    float a1 = p * Wlin[2 * t + 1];
#pragma unroll
    for (int o = 16; o; o >>= 1) {
        a0 += __shfl_xor_sync(0xffffffffu, a0, o);
        a1 += __shfl_xor_sync(0xffffffffu, a1, o);
    }
    __shared__ float sa[4], sb2[4];
    if ((t & 31) == 0) { sa[t >> 5] = a0; sb2[t >> 5] = a1; }
    __syncthreads();
    if (t == 0) out[2 * g + 0] = sa[0] + sa[1] + sa[2] + sa[3] + blin[0];
    if (t == 1) out[2 * g + 1] = sb2[0] + sb2[1] + sb2[2] + sb2[3] + blin[1];
}

// ---------------- launcher ----------------
extern "C" void kernel_launch(void* const* d_in, const int* in_sizes, int n_in,
                              void* d_out, int out_size) {
    const float* x     = (const float*)d_in[0];
    const int*   ei    = (const int*)d_in[1];
    const int*   batch = (const int*)d_in[2];
    const float* Wl1   = (const float*)d_in[3];
    const float* Wr1   = (const float*)d_in[4];
    const float* att1  = (const float*)d_in[5];
    const float* b1    = (const float*)d_in[6];
    const float* gamma = (const float*)d_in[7];
    const float* beta  = (const float*)d_in[8];
    const float* Wl2   = (const float*)d_in[9];
    const float* Wr2   = (const float*)d_in[10];
    const float* att2  = (const float*)d_in[11];
    const float* b2    = (const float*)d_in[12];
    const float* Wlin  = (const float*)d_in[13];
    const float* blin  = (const float*)d_in[14];
    float* out = (float*)d_out;

    void *p_y1, *p_h1, *p_y2, *p_b1, *p_b2;
    cudaGetSymbolAddress(&p_y1, g_y1);
    cudaGetSymbolAddress(&p_h1, g_h1);
    cudaGetSymbolAddress(&p_y2, g_y2);
    cudaGetSymbolAddress(&p_b1, g_B1);
    cudaGetSymbolAddress(&p_b2, g_B2);
    __half* y1 = (__half*)p_y1;
    __half* h1 = (__half*)p_h1;
    __half* y2 = (__half*)p_y2;

    const int SMEMSZ = 40960 + 2048;  // 2 pipeline stages + BN scale/shift
    static bool s_init = false;
    static cudaStream_t s1;
    static cudaEvent_t evFork, evJoin;
    if (!s_init) {
        cudaFuncSetAttribute(k_mma<128, false, float>, cudaFuncAttributeMaxDynamicSharedMemorySize, SMEMSZ);
        cudaFuncSetAttribute(k_mma<256, true, __half>, cudaFuncAttributeMaxDynamicSharedMemorySize, SMEMSZ);
        cudaStreamCreateWithFlags(&s1, cudaStreamNonBlocking);
        cudaEventCreateWithFlags(&evFork, cudaEventDisableTiming);
        cudaEventCreateWithFlags(&evJoin, cudaEventDisableTiming);
        s_init = true;
    }

    const int MB = (NN + 127) / 128;  // 391

    // ---- fork: CSR build on side stream, GEMM path on main stream ----
    cudaEventRecord(evFork, 0);
    cudaStreamWaitEvent(s1, evFork, 0);

    // main stream: weight convert -> layer1 GEMM
    k_initMain<<<256, 256>>>();
    k_cvtB<<<512, 256>>>(Wl1, Wr1, Wl2, Wr2);
    k_mma<128, false, float><<<dim3(4, MB), 256, SMEMSZ>>>(
        x, (const __half*)p_b1, y1, 512, NN);

    // side stream: CSR build (independent of GEMM path)
    k_initDeg<<<(NN + 255) / 256, 256, 0, s1>>>();
    k_hist<<<(ET + 255) / 256, 256, 0, s1>>>(ei);
    k_scanA<<<SCB, 1024, 0, s1>>>();
    k_scanB<<<1, 32, 0, s1>>>();
    k_scanC<<<SCB, 1024, 0, s1>>>();
    k_fill<<<(ET + 255) / 256, 256, 0, s1>>>(ei);
    cudaEventRecord(evJoin, s1);
    cudaStreamWaitEvent(0, evJoin, 0);

    // ---- joined: aggregation needs both y1 and CSR ----
    k_agg<2, false><<<(NN * 32 + 255) / 256, 256>>>(y1, att1, b1, h1, nullptr);

    // BatchNorm stats -> affine folded into layer-2 GEMM A-loads
    k_bnstats<<<512, 256>>>(h1);
    k_bnfin<<<1, 256>>>(gamma, beta);

    // Layer 2: y2 = bn(h1) @ [Wl2 | Wr2]
    k_mma<256, true, __half><<<dim3(2, MB), 256, SMEMSZ>>>(
        h1, (const __half*)p_b2, y2, 256, NN);
    k_agg<1, true><<<(NN * 32 + 255) / 256, 256>>>(y2, att2, b2, nullptr, batch);

    // Pool mean + final linear
    k_final<<<GG, 128>>>(Wlin, blin, out);
}

// round 12
// speedup vs baseline: 2.1493x; 1.0873x over previous
#include <cuda_runtime.h>
#include <cuda_fp16.h>
#include <math.h>
#include <stdint.h>

#define NN 50000
#define EE 800000
#define ET 850000   // EE + NN self loops
#define GG 512
#define SCB 25      // scan blocks (2048 elems each)

// ---------------- static scratch (no allocations allowed) ----------------
__device__ __align__(128) __half g_y1[(size_t)NN * 512];  // [xl1 | xr1] fp16
__device__ __align__(128) __half g_h1[(size_t)NN * 256];  // post-ELU layer1 output fp16
__device__ __align__(128) __half g_y2[(size_t)NN * 256];  // [xl2 | xr2] fp16
__device__ __align__(128) __half g_B1[512 * 128];  // layer1 B^T fp16 [n][k]
__device__ __align__(128) __half g_B2[256 * 256];  // layer2 B^T fp16 [n][k]
__device__ int    g_deg[NN];
__device__ int    g_off[NN + 1];
__device__ int    g_cur[NN];
__device__ int    g_csrc[ET];
__device__ int    g_blksum[32];
__device__ double g_bnsum[256];
__device__ double g_bnsq[256];
__device__ float  g_scale[256];
__device__ float  g_shift[256];
__device__ float  g_pool[GG * 128];
__device__ float  g_cnt[GG];

// ---------------- PTX helpers (baseline sm_80/sm_90 features only) ----------------
__device__ __forceinline__ uint32_t smem_u32(const void* p) {
    uint32_t r;
    asm("{ .reg .u64 t; cvta.to.shared.u64 t, %1; cvt.u32.u64 %0, t; }" : "=r"(r) : "l"(p));
    return r;
}
#define CP_ASYNC16(dst, src) \
    asm volatile("cp.async.cg.shared.global [%0], [%1], 16;" :: "r"(dst), "l"(src) : "memory")
#define CP_COMMIT() asm volatile("cp.async.commit_group;" ::: "memory")
#define CP_WAIT(n)  asm volatile("cp.async.wait_group %0;" :: "n"(n) : "memory")
#define LDM_X4(r0, r1, r2, r3, addr) \
    asm volatile("ldmatrix.sync.aligned.m8n8.x4.shared.b16 {%0,%1,%2,%3}, [%4];" \
        : "=r"(r0), "=r"(r1), "=r"(r2), "=r"(r3) : "r"(addr))
#define MMA_F16(cc, a, b0v, b1v) \
    asm volatile("mma.sync.aligned.m16n8k16.row.col.f32.f16.f16.f32 " \
        "{%0,%1,%2,%3}, {%4,%5,%6,%7}, {%8,%9}, {%0,%1,%2,%3};" \
        : "+f"((cc)[0]), "+f"((cc)[1]), "+f"((cc)[2]), "+f"((cc)[3]) \
        : "r"((a)[0]), "r"((a)[1]), "r"((a)[2]), "r"((a)[3]), "r"(b0v), "r"(b1v))

__device__ __forceinline__ uint32_t pkh2(float a, float b) {
    __half2 t = __floats2half2_rn(a, b);
    return *reinterpret_cast<uint32_t*>(&t);
}

// ---------------- init ----------------
__global__ void k_initMain() {
    int i = blockIdx.x * blockDim.x + threadIdx.x;  // 65536 threads
    if (i < GG * 128) g_pool[i] = 0.f;
    if (i < GG) g_cnt[i] = 0.f;
    if (i < 256) { g_bnsum[i] = 0.0; g_bnsq[i] = 0.0; }
    if (i < NN) g_deg[i] = 0;
}

// ---------------- convert & transpose weights (fp16) ----------------
__global__ void k_cvtB(const float* __restrict__ Wl1, const float* __restrict__ Wr1,
                       const float* __restrict__ Wl2, const float* __restrict__ Wr2) {
    int i = blockIdx.x * blockDim.x + threadIdx.x;  // 131072 threads
    if (i < 512 * 128) {
        int n = i >> 7, k = i & 127;
        float w = (n < 256) ? Wl1[k * 256 + n] : Wr1[k * 256 + (n - 256)];
        g_B1[i] = __float2half(w);
    } else if (i < 512 * 128 + 256 * 256) {
        int j = i - 512 * 128;
        int n = j >> 8, k = j & 255;
        float w = (n < 128) ? Wl2[k * 128 + n] : Wr2[k * 128 + (n - 128)];
        g_B2[j] = __float2half(w);
    }
}

// ---------------- CSR build ----------------
__global__ void k_hist(const int* __restrict__ ei) {
    int i = blockIdx.x * blockDim.x + threadIdx.x;
    if (i >= ET) return;
    int dst = (i < EE) ? ei[EE + i] : (i - EE);
    atomicAdd(&g_deg[dst], 1);
}

// hierarchical scan: A) block sums, B) scan block sums, C) full scan + write
__global__ void k_scanA() {  // grid SCB, block 1024
    __shared__ int ws[32];
    const int b = blockIdx.x, t = threadIdx.x;
    const int i = b * 2048 + 2 * t;
    int v0 = 0, v1 = 0;
    if (i + 1 < NN) { int2 p = *(const int2*)&g_deg[i]; v0 = p.x; v1 = p.y; }
    else if (i < NN) v0 = g_deg[i];
    int s = v0 + v1;
#pragma unroll
    for (int o = 16; o; o >>= 1) s += __shfl_xor_sync(0xffffffffu, s, o);
    if ((t & 31) == 0) ws[t >> 5] = s;
    __syncthreads();
    if (t < 32) {
        int x = ws[t];
#pragma unroll
        for (int o = 16; o; o >>= 1) x += __shfl_xor_sync(0xffffffffu, x, o);
        if (t == 0) g_blksum[b] = x;
    }
}

__global__ void k_scanB() {  // 1 block, 32 threads: exclusive scan of SCB sums
    int t = threadIdx.x;
    int v = (t < SCB) ? g_blksum[t] : 0;
    int x = v;
#pragma unroll
    for (int o = 1; o < 32; o <<= 1) {
        int u = __shfl_up_sync(0xffffffffu, x, o);
        if (t >= o) x += u;
    }
    if (t < SCB) g_blksum[t] = x - v;  // exclusive
    if (t == SCB - 1) g_off[NN] = x;   // grand total
}

__global__ void k_scanC() {  // grid SCB, block 1024: full scan + write off/cur
    __shared__ int ws[32];
    const int b = blockIdx.x, t = threadIdx.x;
    const int lane = t & 31, w = t >> 5;
    const int i = b * 2048 + 2 * t;
    int v0 = 0, v1 = 0;
    if (i + 1 < NN) { int2 p = *(const int2*)&g_deg[i]; v0 = p.x; v1 = p.y; }
    else if (i < NN) v0 = g_deg[i];
    int s = v0 + v1;
    int x = s;
#pragma unroll
    for (int o = 1; o < 32; o <<= 1) {
        int u = __shfl_up_sync(0xffffffffu, x, o);
        if (lane >= o) x += u;
    }
    if (lane == 31) ws[w] = x;
    __syncthreads();
    if (w == 0) {
        int y = ws[lane];
#pragma unroll
        for (int o = 1; o < 32; o <<= 1) {
            int u = __shfl_up_sync(0xffffffffu, y, o);
            if (lane >= o) y += u;
        }
        ws[lane] = y;
    }
    __syncthreads();
    int excl = x - s + (w > 0 ? ws[w - 1] : 0) + g_blksum[b];
    if (i < NN) { g_off[i] = excl; g_cur[i] = excl; }
    if (i + 1 < NN) { g_off[i + 1] = excl + v0; g_cur[i + 1] = excl + v0; }
}

__global__ void k_fill(const int* __restrict__ ei) {
    int i = blockIdx.x * blockDim.x + threadIdx.x;
    if (i >= ET) return;
    int src = (i < EE) ? ei[i] : (i - EE);
    int dst = (i < EE) ? ei[EE + i] : (i - EE);
    int p = atomicAdd(&g_cur[dst], 1);
    g_csrc[p] = src;
}

// ---------------- single-pass fp16 mma.sync GEMM ----------------
template <int K, bool NORM, typename TA>
__global__ void __launch_bounds__(256, 2) k_mma(
    const TA* __restrict__ A,
    const __half* __restrict__ B,
    __half* __restrict__ C, int ldc, int M) {
    extern __shared__ __align__(128) char smem[];
    constexpr int NC = K / 32;
    const int tid = threadIdx.x, lane = tid & 31, wid = tid >> 5;
    const int row0 = blockIdx.y * 128, n0 = blockIdx.x * 128;
    const int wm = (wid & 3) * 32, wn = (wid >> 2) * 64;
    const uint32_t sb = smem_u32(smem);
    float* sScale = (float*)(smem + 40960);
    float* sShift = (float*)(smem + 40960 + 1024);

    if (NORM) {
        if (tid < K) { sScale[tid] = g_scale[tid]; sShift[tid] = g_shift[tid]; }
        __syncthreads();
    }

    float c[2][8][4];
#pragma unroll
    for (int mf = 0; mf < 2; mf++)
#pragma unroll
        for (int nf = 0; nf < 8; nf++)
#pragma unroll
            for (int q = 0; q < 4; q++) c[mf][nf][q] = 0.f;

    const int ar = tid >> 1;             // A row within tile
    const int ac = (tid & 1) * 16;       // A col-seg within chunk
    const int agr = min(row0 + ar, M - 1);

    auto ldgA = [&](int ch, float* f) {
        const TA* ap = A + (size_t)agr * K + ch * 32 + ac;
        if (sizeof(TA) == 4) {
            const float* fp = (const float*)ap;
#pragma unroll
            for (int q = 0; q < 4; q++) {
                float4 v = *(const float4*)(fp + q * 4);
                f[q * 4 + 0] = v.x; f[q * 4 + 1] = v.y;
                f[q * 4 + 2] = v.z; f[q * 4 + 3] = v.w;
            }
        } else {
            const __half2* hp = (const __half2*)ap;
#pragma unroll
            for (int q = 0; q < 8; q++) {
                float2 v = __half22float2(hp[q]);
                f[q * 2 + 0] = v.x; f[q * 2 + 1] = v.y;
            }
        }
    };
    auto stsA = [&](int ch, float* f) {
        const uint32_t base = (uint32_t)(ch & 1) * 20480u;
        if (NORM) {
            const int c0 = ch * 32 + ac;
#pragma unroll
            for (int i = 0; i < 16; i++) f[i] = fmaf(f[i], sScale[c0 + i], sShift[c0 + i]);
        }
        uint4 H0 = make_uint4(pkh2(f[0], f[1]), pkh2(f[2], f[3]), pkh2(f[4], f[5]), pkh2(f[6], f[7]));
        uint4 H1 = make_uint4(pkh2(f[8], f[9]), pkh2(f[10], f[11]), pkh2(f[12], f[13]), pkh2(f[14], f[15]));
        const uint32_t off = base + (uint32_t)ar * 80u + (uint32_t)ac * 2u;
        *(uint4*)(smem + off) = H0;
        *(uint4*)(smem + off + 16) = H1;
    };
    auto issueB = [&](int ch) {
        const int k0 = ch * 32;
        const uint32_t base = sb + (uint32_t)(ch & 1) * 20480u + 10240u;
#pragma unroll
        for (int j = 0; j < 2; j++) {
            int seg = tid + 256 * j;
            int r = seg >> 2, s = seg & 3;
            const void* src = B + (size_t)(n0 + r) * K + k0 + s * 8;
            uint32_t dst = base + (uint32_t)r * 80u + (uint32_t)s * 16u;
            CP_ASYNC16(dst, src);
        }
    };

    // prologue
    float areg[16];
    ldgA(0, areg);
    stsA(0, areg);
    issueB(0);
    CP_COMMIT();
    if (NC > 1) {
        issueB(1);
        CP_COMMIT();
        ldgA(1, areg);
    }

    // ldmatrix per-lane address pieces
    const int grp = lane >> 3, r8 = lane & 7;
    const uint32_t a_row = (uint32_t)(((grp & 1) ? 8 : 0) + r8);
    const uint32_t a_k16 = (grp & 2) ? 16u : 0u;
    const uint32_t b_row = (uint32_t)(((grp & 2) ? 8 : 0) + r8);
    const uint32_t b_k16 = (grp & 1) ? 16u : 0u;

    for (int ch = 0; ch < NC; ch++) {
        if (ch + 1 < NC) { CP_WAIT(1); } else { CP_WAIT(0); }
        __syncthreads();
        const uint32_t sA = sb + (uint32_t)(ch & 1) * 20480u;
#pragma unroll
        for (int ks = 0; ks < 2; ks++) {
            const uint32_t ko = (uint32_t)ks * 32u;
            uint32_t ah[2][4], bh[4][4];
#pragma unroll
            for (int mf = 0; mf < 2; mf++) {
                uint32_t addr = sA + ((uint32_t)(wm + mf * 16) + a_row) * 80u + ko + a_k16;
                LDM_X4(ah[mf][0], ah[mf][1], ah[mf][2], ah[mf][3], addr);
            }
#pragma unroll
            for (int pf = 0; pf < 4; pf++) {
                uint32_t addr = sA + 10240u + ((uint32_t)(wn + pf * 16) + b_row) * 80u + ko + b_k16;
                LDM_X4(bh[pf][0], bh[pf][1], bh[pf][2], bh[pf][3], addr);
            }
#pragma unroll
            for (int mf = 0; mf < 2; mf++)
#pragma unroll
                for (int nf = 0; nf < 8; nf++) {
                    const int pf = nf >> 1, h = (nf & 1) * 2;
                    MMA_F16(c[mf][nf], ah[mf], bh[pf][h], bh[pf][h + 1]);
                }
        }
        if (ch + 1 < NC) {
            stsA(ch + 1, areg);               // other buffer: safe pre-sync
            if (ch + 2 < NC) ldgA(ch + 2, areg);
        }
        __syncthreads();
        if (ch + 2 < NC) {
            issueB(ch + 2);                    // reuses buffer (ch&1): safe post-sync
            CP_COMMIT();
        }
    }

    // epilogue (fp16 stores)
    const int g = lane >> 2, tg = lane & 3;
#pragma unroll
    for (int mf = 0; mf < 2; mf++) {
        int row = row0 + wm + mf * 16 + g;
#pragma unroll
        for (int nf = 0; nf < 8; nf++) {
            int col = n0 + wn + nf * 8 + 2 * tg;
            if (row < M)
                *(__half2*)(C + (size_t)row * ldc + col) = __floats2half2_rn(c[mf][nf][0], c[mf][nf][1]);
            if (row + 8 < M)
                *(__half2*)(C + (size_t)(row + 8) * ldc + col) = __floats2half2_rn(c[mf][nf][2], c[mf][nf][3]);
        }
    }
}

// ---------------- GATv2 aggregation: warp per dst node, branch-free online softmax ----
// Lane owns a contiguous block of NCH channels (one 8/16-byte vector load per edge).
// Per-head dot reduced over LPH = 32/HEADS lanes (segmented butterfly).
template <int HEADS, bool FINAL>
__global__ void k_agg(const __half* __restrict__ y,     // [NN, 2*CH] = [xl | xr] fp16
                      const float* __restrict__ att,    // [CH]
                      const float* __restrict__ bias,   // [CH]
                      __half* __restrict__ hout,        // [NN, CH] fp16 (if !FINAL)
                      const int* __restrict__ batch) {
    constexpr int CH = HEADS * 128;
    constexpr int NCH = CH / 32;       // channels per lane (8 or 4)
    constexpr int NH2 = NCH / 2;       // half2 per lane (4 or 2)
    constexpr int LPH = 32 / HEADS;    // lanes per head
    const int lane = threadIdx.x & 31;
    const int t = (blockIdx.x * blockDim.x + threadIdx.x) >> 5;
    if (t >= NN) return;
    const int c0 = NCH * lane;         // this lane's first channel

    const __half* yt = y + (size_t)t * (2 * CH) + CH + c0;  // xr[t] block
    float2 xr[NH2], attv[NH2], acc[NH2];
#pragma unroll
    for (int k = 0; k < NH2; k++) {
        xr[k] = __half22float2(*(const __half2*)(yt + 2 * k));
        attv[k] = make_float2(att[c0 + 2 * k], att[c0 + 2 * k + 1]);
        acc[k] = make_float2(0.f, 0.f);
    }
    float emax = -1e30f, den = 0.f;

    const int s0 = g_off[t], s1 = g_off[t + 1];
#pragma unroll 2
    for (int j = s0; j < s1; j++) {
        int s = g_csrc[j];
        const __half* ys = y + (size_t)s * (2 * CH) + c0;  // xl[s] block
        uint32_t vr[NH2];
        if (NH2 == 4) {
            uint4 u = *(const uint4*)ys;
            vr[0] = u.x; vr[1] = u.y; vr[2] = u.z; vr[3] = u.w;
        } else {
            uint2 u = *(const uint2*)ys;
            vr[0] = u.x; vr[1] = u.y;
        }
        float2 xv[NH2];
        float d = 0.f;
#pragma unroll
        for (int k = 0; k < NH2; k++) {
            float2 v = __half22float2(*reinterpret_cast<__half2*>(&vr[k]));
            xv[k] = v;
            float mx = v.x + xr[k].x;
            float my = v.y + xr[k].y;
            mx = fmaxf(mx, 0.2f * mx);   // leaky relu
            my = fmaxf(my, 0.2f * my);
            d = fmaf(mx, attv[k].x, d);
            d = fmaf(my, attv[k].y, d);
        }
#pragma unroll
        for (int o = LPH >> 1; o; o >>= 1) d += __shfl_xor_sync(0xffffffffu, d, o);

        float nm = fmaxf(emax, d);
        float corr = __expf(emax - nm);
        float ex = __expf(d - nm);
        emax = nm;
        den = fmaf(den, corr, ex);
#pragma unroll
        for (int k = 0; k < NH2; k++) {
            acc[k].x = fmaf(acc[k].x, corr, ex * xv[k].x);
            acc[k].y = fmaf(acc[k].y, corr, ex * xv[k].y);
        }
    }

    const float inv = 1.f / (den + 1e-16f);
    if (FINAL) {
        int g = batch[t];
#pragma unroll
        for (int k = 0; k < NH2; k++) {
            atomicAdd(&g_pool[g * 128 + c0 + 2 * k], acc[k].x * inv + bias[c0 + 2 * k]);
            atomicAdd(&g_pool[g * 128 + c0 + 2 * k + 1], acc[k].y * inv + bias[c0 + 2 * k + 1]);
        }
        if (lane == 0) atomicAdd(&g_cnt[g], 1.f);
    } else {
        uint32_t o[NH2];
#pragma unroll
        for (int k = 0; k < NH2; k++) {
            float vx = acc[k].x * inv + bias[c0 + 2 * k];
            float vy = acc[k].y * inv + bias[c0 + 2 * k + 1];
            vx = (vx > 0.f) ? vx : expm1f(vx);  // ELU
            vy = (vy > 0.f) ? vy : expm1f(vy);
            o[k] = pkh2(vx, vy);
        }
        __half* hp = hout + (size_t)t * CH + c0;
        if (NH2 == 4) *(uint4*)hp = make_uint4(o[0], o[1], o[2], o[3]);
        else          *(uint2*)hp = make_uint2(o[0], o[1]);
    }
}

// ---------------- BatchNorm stats + finalize ----------------
__global__ void k_bnstats(const __half* __restrict__ h) {
    int c = threadIdx.x;  // 256
    float s = 0.f, q = 0.f;
    for (int r = blockIdx.x; r < NN; r += gridDim.x) {
        float v = __half2float(h[(size_t)r * 256 + c]);
        s += v;
        q = fmaf(v, v, q);
    }
    atomicAdd(&g_bnsum[c], (double)s);
    atomicAdd(&g_bnsq[c], (double)q);
}

__global__ void k_bnfin(const float* __restrict__ gamma, const float* __restrict__ beta) {
    int c = threadIdx.x;  // 256
    float mu = (float)(g_bnsum[c] / (double)NN);
    float var = (float)(g_bnsq[c] / (double)NN) - mu * mu;
    float sc = gamma[c] * rsqrtf(var + 1e-5f);
    g_scale[c] = sc;
    g_shift[c] = beta[c] - mu * sc;
}

// ---------------- final: pooled mean @ Wlin + blin ----------------
__global__ void k_final(const float* __restrict__ Wlin, const float* __restrict__ blin,
                        float* __restrict__ out) {
    int g = blockIdx.x;        // GG blocks
    int t = threadIdx.x;       // 128 threads
    float inv = 1.f / fmaxf(g_cnt[g], 1.f);
    float p = g_pool[g * 128 + t] * inv;
    float a0 = p * Wlin[2 * t + 0];
    float a1 = p * Wlin[2 * t + 1];
#pragma unroll
    for (int o = 16; o; o >>= 1) {
        a0 += __shfl_xor_sync(0xffffffffu, a0, o);
        a1 += __shfl_xor_sync(0xffffffffu, a1, o);
    }
    __shared__ float sa[4], sb2[4];
    if ((t & 31) == 0) { sa[t >> 5] = a0; sb2[t >> 5] = a1; }
    __syncthreads();
    if (t == 0) out[2 * g + 0] = sa[0] + sa[1] + sa[2] + sa[3] + blin[0];
    if (t == 1) out[2 * g + 1] = sb2[0] + sb2[1] + sb2[2] + sb2[3] + blin[1];
}

// ---------------- launcher ----------------
extern "C" void kernel_launch(void* const* d_in, const int* in_sizes, int n_in,
                              void* d_out, int out_size) {
    const float* x     = (const float*)d_in[0];
    const int*   ei    = (const int*)d_in[1];
    const int*   batch = (const int*)d_in[2];
    const float* Wl1   = (const float*)d_in[3];
    const float* Wr1   = (const float*)d_in[4];
    const float* att1  = (const float*)d_in[5];
    const float* b1    = (const float*)d_in[6];
    const float* gamma = (const float*)d_in[7];
    const float* beta  = (const float*)d_in[8];
    const float* Wl2   = (const float*)d_in[9];
    const float* Wr2   = (const float*)d_in[10];
    const float* att2  = (const float*)d_in[11];
    const float* b2    = (const float*)d_in[12];
    const float* Wlin  = (const float*)d_in[13];
    const float* blin  = (const float*)d_in[14];
    float* out = (float*)d_out;

    void *p_y1, *p_h1, *p_y2, *p_b1, *p_b2;
    cudaGetSymbolAddress(&p_y1, g_y1);
    cudaGetSymbolAddress(&p_h1, g_h1);
    cudaGetSymbolAddress(&p_y2, g_y2);
    cudaGetSymbolAddress(&p_b1, g_B1);
    cudaGetSymbolAddress(&p_b2, g_B2);
    __half* y1 = (__half*)p_y1;
    __half* h1 = (__half*)p_h1;
    __half* y2 = (__half*)p_y2;

    const int SMEMSZ = 40960 + 2048;  // 2 pipeline stages + BN scale/shift
    static bool s_init = false;
    static cudaStream_t s1;
    static cudaEvent_t evFork, evJoin;
    if (!s_init) {
        cudaFuncSetAttribute(k_mma<128, false, float>, cudaFuncAttributeMaxDynamicSharedMemorySize, SMEMSZ);
        cudaFuncSetAttribute(k_mma<256, true, __half>, cudaFuncAttributeMaxDynamicSharedMemorySize, SMEMSZ);
        cudaStreamCreateWithFlags(&s1, cudaStreamNonBlocking);
        cudaEventCreateWithFlags(&evFork, cudaEventDisableTiming);
        cudaEventCreateWithFlags(&evJoin, cudaEventDisableTiming);
        s_init = true;
    }

    const int MB = (NN + 127) / 128;  // 391

    // main stream: init (incl. deg) -> fork -> weight convert -> layer1 GEMM
    k_initMain<<<256, 256>>>();
    cudaEventRecord(evFork, 0);
    cudaStreamWaitEvent(s1, evFork, 0);

    k_cvtB<<<512, 256>>>(Wl1, Wr1, Wl2, Wr2);
    k_mma<128, false, float><<<dim3(4, MB), 256, SMEMSZ>>>(
        x, (const __half*)p_b1, y1, 512, NN);

    // side stream: CSR build (independent of GEMM path)
    k_hist<<<(ET + 255) / 256, 256, 0, s1>>>(ei);
    k_scanA<<<SCB, 1024, 0, s1>>>();
    k_scanB<<<1, 32, 0, s1>>>();
    k_scanC<<<SCB, 1024, 0, s1>>>();
    k_fill<<<(ET + 255) / 256, 256, 0, s1>>>(ei);
    cudaEventRecord(evJoin, s1);
    cudaStreamWaitEvent(0, evJoin, 0);

    // ---- joined: aggregation needs both y1 and CSR ----
    k_agg<2, false><<<(NN * 32 + 255) / 256, 256>>>(y1, att1, b1, h1, nullptr);

    // BatchNorm stats -> affine folded into layer-2 GEMM A-loads
    k_bnstats<<<512, 256>>>(h1);
    k_bnfin<<<1, 256>>>(gamma, beta);

    // Layer 2: y2 = bn(h1) @ [Wl2 | Wr2]
    k_mma<256, true, __half><<<dim3(2, MB), 256, SMEMSZ>>>(
        h1, (const __half*)p_b2, y2, 256, NN);
    k_agg<1, true><<<(NN * 32 + 255) / 256, 256>>>(y2, att2, b2, nullptr, batch);

    // Pool mean + final linear
    k_final<<<GG, 128>>>(Wlin, blin, out);
}